// round 12
// baseline (speedup 1.0000x reference)
#include <cuda_runtime.h>
#include <cuda_bf16.h>
#include <math.h>
#include <stdint.h>
#include <mma.h>

using namespace nvcuda;

// ---------------- problem constants ----------------
#define Bq 16
#define Cq 256
#define Hq 64
#define Wq 64
#define Nq 4096
#define NHq 8
#define CRq 128
#define HIDq 1024
#define HALFq 512
#define Mrows (Bq*Nq)      // 65536

// ---------------- scratch layout (float units) ----------------
#define OFF_MH    0ull
#define OFF_MW    262144ull
#define OFF_GH    524288ull
#define OFF_GW    786432ull
#define OFF_RES1  1048576ull      // f32  [M,256]
#define OFF_LNB   17825792ull     // bf16 [M,256]
#define OFF_QB    26214400ull     // bf16 [M,128]
#define OFF_R1    30408704ull     // f32  [B,256,256]
#define OFF_R2    31457280ull     // f32  [B,16,256]
#define OFF_D     31522816ull     // f32  [B,16,256]
#define OFF_XA    31588352ull     // f32  [B,16,128]
#define OFF_K     31621120ull     // f32  [B,16,128]
#define OFF_VT    31653888ull     // f32  [B,16,256]
#define OFF_V2    31719424ull     // f32  [B,16,256]
#define OFF_AOB   31784960ull     // bf16 [M,256]
#define OFF_T2    40173568ull     // f32  [M,256]
#define OFF_LN2B  56950784ull     // bf16 [M,256]
#define OFF_X1B   65339392ull     // bf16 [M,512]
#define OFF_X2B   82116608ull     // bf16 [M,512]
#define OFF_X2LN  98893824ull     // bf16 [M,512]
#define OFF_GTB   115671040ull    // bf16 [M,512]
#define OFF_WTQ   132448256ull    // bf16 [128,256]
#define OFF_WTP   132464640ull    // bf16 [256,256]
#define OFF_WT1   132497408ull    // bf16 [1024,256]
#define OFF_WT2   132628480ull    // bf16 [256,512]
#define G_TOTAL   132694016ull

static __device__ float g_s[G_TOTAL];

#define DINL __device__ __forceinline__

DINL float gelu_f(float x) { return 0.5f * x * (1.0f + erff(x * 0.70710678118654752f)); }
DINL __nv_bfloat16 f2b(float x) { return __float2bfloat16_rn(x); }

DINL void blockReduce2(float& s, float& q, float* sh) {
    int lane = threadIdx.x & 31, wid = threadIdx.x >> 5;
#pragma unroll
    for (int o = 16; o > 0; o >>= 1) {
        s += __shfl_down_sync(0xffffffffu, s, o);
        q += __shfl_down_sync(0xffffffffu, q, o);
    }
    if (lane == 0) { sh[wid] = s; sh[32 + wid] = q; }
    __syncthreads();
    if (threadIdx.x == 0) {
        float ss = 0.f, qq = 0.f;
        int nw = blockDim.x >> 5;
        for (int i = 0; i < nw; i++) { ss += sh[i]; qq += sh[32 + i]; }
        sh[0] = ss; sh[32] = qq;
    }
    __syncthreads();
    s = sh[0]; q = sh[32];
}

// ================= wmma bf16 GEMM, 4-stage pipeline, K templated =================
// C = A[M,KT] @ BT[N,KT]^T. OP bits: 1 bias, 2 gelu, 4 residual,
// 8 split-bf16 (fc1), 16 transposed f32 (fc2 -> [B,C,HW]), 32 plain bf16 (q).
// CTA 128x128, K-chunk 32, 256 threads (8 warps 2x4, 64x32 each), 4-stage cp.async.
#define KC 32
#define LDE 40                       // bf16 elems per smem row (32 data + 8 pad = 80B)
#define STG_E (256*LDE)              // elems per stage = 10240
#define NSTG 4
#define DSMB (NSTG*STG_E*2)          // 81920 bytes

template <int OP, int KT>
__global__ __launch_bounds__(256) void k_bf_gemm(const __nv_bfloat16* __restrict__ A,
        const __nv_bfloat16* __restrict__ BT, const float* __restrict__ bias,
        const float* __restrict__ res, void* __restrict__ Cv, void* __restrict__ C2v,
        int M, int N) {
    extern __shared__ __align__(16) char dsm[];
    __nv_bfloat16* sm = (__nv_bfloat16*)dsm;
    __shared__ float sbias[128];
    int tid = threadIdx.x;
    int m0 = blockIdx.y << 7, n0 = blockIdx.x << 7;
    if ((OP & 1) && tid < 128) sbias[tid] = bias[n0 + tid];

    int w = tid >> 5;
    int wm = w >> 2, wn = w & 3;     // 2x4 warps: 64-row x 32-col tiles

    wmma::fragment<wmma::accumulator, 16, 16, 16, float> acc[4][2];
#pragma unroll
    for (int mi = 0; mi < 4; mi++)
#pragma unroll
        for (int ni = 0; ni < 2; ni++) wmma::fill_fragment(acc[mi][ni], 0.f);

    int seg = tid & 3, r0 = tid >> 2;
    const __nv_bfloat16* Ag = A + (size_t)(m0 + r0) * KT + seg * 8;
    const __nv_bfloat16* Bg = BT + (size_t)(n0 + r0) * KT + seg * 8;
    uint32_t sbase = (uint32_t)__cvta_generic_to_shared(sm);
    constexpr int NK = KT >> 5;

#define ISSUE_CHUNK(i)                                                                \
    {                                                                                 \
        uint32_t ba = sbase + (uint32_t)(((i) & 3) * (STG_E * 2))                     \
                    + (uint32_t)(r0 * 80 + seg * 16);                                 \
        const __nv_bfloat16* ga = Ag + (i) * KC;                                      \
        const __nv_bfloat16* gb = Bg + (i) * KC;                                      \
        _Pragma("unroll")                                                             \
        for (int it = 0; it < 2; it++)                                                \
            asm volatile("cp.async.cg.shared.global [%0], [%1], 16;"                  \
                :: "r"(ba + it * (64u * 80u)), "l"(ga + (size_t)it * 64 * KT)         \
                : "memory");                                                          \
        _Pragma("unroll")                                                             \
        for (int it = 0; it < 2; it++)                                                \
            asm volatile("cp.async.cg.shared.global [%0], [%1], 16;"                  \
                :: "r"(ba + 10240u + it * (64u * 80u)), "l"(gb + (size_t)it * 64 * KT)\
                : "memory");                                                          \
        asm volatile("cp.async.commit_group;");                                       \
    }

    ISSUE_CHUNK(0); ISSUE_CHUNK(1); ISSUE_CHUNK(2);
#pragma unroll
    for (int i = 0; i < NK; i++) {
        asm volatile("cp.async.wait_group 2;");
        __syncthreads();
        if (i + 3 < NK) { ISSUE_CHUNK(i + 3); }
        else { asm volatile("cp.async.commit_group;"); }
        const __nv_bfloat16* As = sm + (i & 3) * STG_E;
        const __nv_bfloat16* Bs = As + 128 * LDE;
#pragma unroll
        for (int kk = 0; kk < KC; kk += 16) {
            wmma::fragment<wmma::matrix_a, 16, 16, 16, __nv_bfloat16, wmma::row_major> af[4];
            wmma::fragment<wmma::matrix_b, 16, 16, 16, __nv_bfloat16, wmma::col_major> bf[2];
#pragma unroll
            for (int mi = 0; mi < 4; mi++)
                wmma::load_matrix_sync(af[mi], As + (wm * 64 + mi * 16) * LDE + kk, LDE);
#pragma unroll
            for (int ni = 0; ni < 2; ni++)
                wmma::load_matrix_sync(bf[ni], Bs + (wn * 32 + ni * 16) * LDE + kk, LDE);
#pragma unroll
            for (int mi = 0; mi < 4; mi++)
#pragma unroll
                for (int ni = 0; ni < 2; ni++)
                    wmma::mma_sync(acc[mi][ni], af[mi], bf[ni], acc[mi][ni]);
        }
    }
    __syncthreads();

    float* Cs = (float*)dsm;
#pragma unroll
    for (int mi = 0; mi < 4; mi++)
#pragma unroll
        for (int ni = 0; ni < 2; ni++)
            wmma::store_matrix_sync(Cs + (wm * 64 + mi * 16) * 132 + wn * 32 + ni * 16,
                                    acc[mi][ni], 132, wmma::mem_row_major);
    __syncthreads();

    int col = tid & 127, rr = tid >> 7;
    if (OP & 8) {
        __nv_bfloat16* dst = (n0 < 512) ? (__nv_bfloat16*)Cv : (__nv_bfloat16*)C2v;
        int nloc = n0 & 511;
#pragma unroll 4
        for (int r = rr; r < 128; r += 2) {
            float v = Cs[r * 132 + col] + sbias[col];
            dst[(size_t)(m0 + r) * 512 + nloc + col] = f2b(gelu_f(v));
        }
    } else if (OP & 16) {
        const float* Rp = res + (size_t)m0 * N + n0 + col;
#pragma unroll 4
        for (int r = rr; r < 128; r += 2) {
            float v = Cs[r * 132 + col] + sbias[col] + Rp[(size_t)r * N];
            Cs[r * 132 + col] = v;
        }
        __syncthreads();
        int b = m0 >> 12, pix0 = m0 & 4095;
        float* outp = (float*)Cv + (size_t)b * Cq * Nq + pix0;
        int ch = tid >> 7;
        int m = tid & 127;
#pragma unroll 4
        for (int cc = 0; cc < 64; cc++) {
            int c = cc * 2 + ch;
            outp[(size_t)(n0 + c) * Nq + m] = Cs[m * 132 + c];
        }
    } else if (OP & 32) {
        __nv_bfloat16* dst = (__nv_bfloat16*)Cv;
#pragma unroll 4
        for (int r = rr; r < 128; r += 2)
            dst[(size_t)(m0 + r) * N + n0 + col] = f2b(Cs[r * 132 + col]);
    } else {
        float* Cp = (float*)Cv + (size_t)m0 * N + n0 + col;
        const float* Rp = res + (size_t)m0 * N + n0 + col;
#pragma unroll 4
        for (int r = rr; r < 128; r += 2) {
            float v = Cs[r * 132 + col];
            if (OP & 1) v += sbias[col];
            if (OP & 2) v = gelu_f(v);
            if (OP & 4) v += Rp[(size_t)r * N];
            Cp[(size_t)r * N] = v;
        }
    }
}

// ---------------- merged weight transposes: all 4 in one launch ----------------
// block (32,8); 480 flattened 32x32 tiles:
//   [0,32)   q_w    K=256 N=128   (4 x 8)
//   [32,96)  proj_w K=256 N=256   (8 x 8)
//   [96,352) fc1_w  K=256 N=1024  (32 x 8)
//   [352,480) fc2_w K=512 N=256   (8 x 16)
__global__ void k_wt_all(const float* __restrict__ qw, const float* __restrict__ pw,
                         const float* __restrict__ f1w, const float* __restrict__ f2w,
                         __nv_bfloat16* __restrict__ wtq, __nv_bfloat16* __restrict__ wtp,
                         __nv_bfloat16* __restrict__ wt1, __nv_bfloat16* __restrict__ wt2) {
    __shared__ float t[32][33];
    int bid = blockIdx.x;
    const float* w; __nv_bfloat16* wt; int K, N, bx, by;
    if (bid < 32)        { w = qw;  wt = wtq; K = 256; N = 128;  int l = bid;       bx = l & 3;  by = l >> 2; }
    else if (bid < 96)   { w = pw;  wt = wtp; K = 256; N = 256;  int l = bid - 32;  bx = l & 7;  by = l >> 3; }
    else if (bid < 352)  { w = f1w; wt = wt1; K = 256; N = 1024; int l = bid - 96;  bx = l & 31; by = l >> 5; }
    else                 { w = f2w; wt = wt2; K = 512; N = 256;  int l = bid - 352; bx = l & 7;  by = l >> 3; }
    int nb = bx * 32, kb = by * 32;
    int tx = threadIdx.x, ty = threadIdx.y;
#pragma unroll
    for (int j = 0; j < 4; j++)
        t[ty + j * 8][tx] = w[(size_t)(kb + ty + j * 8) * N + nb + tx];
    __syncthreads();
#pragma unroll
    for (int j = 0; j < 4; j++)
        wt[(size_t)(nb + ty + j * 8) * K + kb + tx] = f2b(t[tx][ty + j * 8]);
}

// ---------------- K1: coordinate pooled means ----------------
__global__ void k_mean(const float* __restrict__ x, float* __restrict__ mh, float* __restrict__ mw) {
    int bc = blockIdx.x;
    const float* p = x + (size_t)bc * 4096;
    int w = threadIdx.x;
    __shared__ float part[128];
    float colsum = 0.f;
    for (int r = 0; r < 64; r++) {
        float v = p[r * 64 + w];
        colsum += v;
        float s = v;
#pragma unroll
        for (int o = 16; o > 0; o >>= 1) s += __shfl_down_sync(0xffffffffu, s, o);
        if ((w & 31) == 0) part[(w >> 5) * 64 + r] = s;
    }
    __syncthreads();
    mh[(size_t)bc * 64 + w] = (part[w] + part[64 + w]) * (1.f / 64.f);
    mw[(size_t)bc * 64 + w] = colsum * (1.f / 64.f);
}

// ---------------- K2: dwconv1d(k=7) + GroupNorm(16) + ReLU ----------------
__global__ void k_sdagn(const float* __restrict__ mh, const float* __restrict__ mw,
                        const float* __restrict__ w7, const float* __restrict__ gnw,
                        const float* __restrict__ gnb, float* __restrict__ gh, float* __restrict__ gw_) {
    int grp = blockIdx.x, b = blockIdx.y;
    const float* mean = (blockIdx.z ? mw : mh) + (size_t)b * Cq * 64;
    float* out = (blockIdx.z ? gw_ : gh) + (size_t)b * Cq * 64;
    __shared__ float buf[1024];
    __shared__ float sh[64];
    int tid = threadIdx.x;
    float ls = 0.f, lq = 0.f;
#pragma unroll
    for (int j = 0; j < 4; j++) {
        int idx = tid + j * 256;
        int c = grp * 16 + (idx >> 6), l = idx & 63;
        const float* m = mean + c * 64;
        float acc = 0.f;
#pragma unroll
        for (int k = 0; k < 7; k++) {
            int ll = l + k - 3;
            if (ll >= 0 && ll < 64) acc += m[ll] * w7[c * 7 + k];
        }
        buf[idx] = acc; ls += acc; lq += acc * acc;
    }
    blockReduce2(ls, lq, sh);
    float mu = ls * (1.f / 1024.f);
    float rstd = rsqrtf(lq * (1.f / 1024.f) - mu * mu + 1e-5f);
#pragma unroll
    for (int j = 0; j < 4; j++) {
        int idx = tid + j * 256;
        int c = grp * 16 + (idx >> 6), l = idx & 63;
        float y = (buf[idx] - mu) * rstd * gnw[c] + gnb[c];
        out[(size_t)c * 64 + l] = fmaxf(y, 0.f);
    }
}

// ---------------- K3: modulate + to tokens + LN1 ----------------
__global__ void k_tokens(const float* __restrict__ x, const float* __restrict__ gh,
                         const float* __restrict__ gw_, const float* __restrict__ n1w,
                         const float* __restrict__ n1b, float* __restrict__ res,
                         __nv_bfloat16* __restrict__ ln) {
    int b = blockIdx.y;
    int n0 = blockIdx.x * 32;
    int h = n0 >> 6, w0 = n0 & 63;
    int nx = threadIdx.x, cy = threadIdx.y;
    __shared__ float tile[256][33];
    __shared__ float mu[32], rs[32];
    const float* ghb = gh + (size_t)b * Cq * 64;
    const float* gwb = gw_ + (size_t)b * Cq * 64;
    const float* xb = x + (size_t)b * Cq * Nq;
#pragma unroll 4
    for (int j = 0; j < 32; j++) {
        int c = cy * 32 + j;
        float v = xb[(size_t)c * Nq + h * 64 + w0 + nx] * ghb[c * 64 + h] * gwb[c * 64 + w0 + nx];
        tile[c][nx] = v;
    }
    __syncthreads();
    int tid = cy * 32 + nx, lane = tid & 31, warp = tid >> 5;
    for (int nn = warp; nn < 32; nn += 8) {
        float s = 0.f, q = 0.f;
        for (int c = lane; c < 256; c += 32) { float v = tile[c][nn]; s += v; q += v * v; }
#pragma unroll
        for (int o = 16; o > 0; o >>= 1) {
            s += __shfl_down_sync(0xffffffffu, s, o);
            q += __shfl_down_sync(0xffffffffu, q, o);
        }
        if (lane == 0) {
            float m = s * (1.f / 256.f);
            mu[nn] = m; rs[nn] = rsqrtf(q * (1.f / 256.f) - m * m + 1e-6f);
        }
    }
    __syncthreads();
    float* resp = res + ((size_t)b * Nq + n0) * Cq;
    __nv_bfloat16* lnp = ln + ((size_t)b * Nq + n0) * Cq;
    for (int idx = tid; idx < 32 * 256; idx += 256) {
        int nl = idx >> 8, c = idx & 255;
        float v = tile[c][nl];
        resp[(size_t)nl * 256 + c] = v;
        lnp[(size_t)nl * 256 + c] = f2b((v - mu[nl]) * rs[nl] * n1w[c] + n1b[c]);
    }
}

// ---------------- reduction path (separate kernels — R8-proven) ----------------
__global__ void k_red1(const __nv_bfloat16* __restrict__ ln1, const float* __restrict__ rw,
                       const float* __restrict__ rb, float* __restrict__ r1) {
    int p = blockIdx.x, b = blockIdx.y, c = threadIdx.x;
    int i = p >> 4, j = p & 15;
    float acc = rb[c];
    const __nv_bfloat16* base = ln1 + (size_t)b * Nq * Cq + c;
#pragma unroll
    for (int a = 0; a < 4; a++)
#pragma unroll
        for (int d = 0; d < 4; d++) {
            int n = (4 * i + a) * 64 + 4 * j + d;
            acc += __bfloat162float(base[(size_t)n * 256]) * rw[c * 16 + a * 4 + d];
        }
    r1[((size_t)b * 256 + p) * 256 + c] = acc;
}

__global__ void k_red2(const float* __restrict__ r1, const float* __restrict__ rw,
                       const float* __restrict__ rb, float* __restrict__ r2) {
    int p2 = blockIdx.x, b = blockIdx.y, c = threadIdx.x;
    int i2 = p2 >> 2, j2 = p2 & 3;
    float acc = rb[c];
#pragma unroll
    for (int a = 0; a < 4; a++)
#pragma unroll
        for (int d = 0; d < 4; d++) {
            int p = (4 * i2 + a) * 16 + (4 * j2 + d);
            acc += r1[((size_t)b * 256 + p) * 256 + c] * rw[c * 16 + a * 4 + d];
        }
    r2[((size_t)b * 16 + p2) * 256 + c] = acc;
}

__global__ void k_dw3(const float* __restrict__ r2, const float* __restrict__ dww,
                      const float* __restrict__ dwb, float* __restrict__ dd) {
    int p = blockIdx.x, b = blockIdx.y, c = threadIdx.x;
    int i = p >> 2, j = p & 3;
    float acc = dwb[c];
#pragma unroll
    for (int a = 0; a < 3; a++) {
        int ii = i + a - 1;
        if (ii < 0 || ii >= 4) continue;
#pragma unroll
        for (int d = 0; d < 3; d++) {
            int jj = j + d - 1;
            if (jj < 0 || jj >= 4) continue;
            acc += r2[((size_t)b * 16 + ii * 4 + jj) * 256 + c] * dww[c * 9 + a * 3 + d];
        }
    }
    dd[((size_t)b * 16 + p) * 256 + c] = acc;
}

__global__ void k_na(const float* __restrict__ dd, const float* __restrict__ cw,
                     const float* __restrict__ cb, const float* __restrict__ naw,
                     const float* __restrict__ nab, float* __restrict__ xa) {
    int p = blockIdx.x, b = blockIdx.y, o = threadIdx.x;
    __shared__ float ds[256];
    __shared__ float sh[64];
    const float* dp = dd + ((size_t)b * 16 + p) * 256;
    ds[o] = dp[o]; ds[o + 128] = dp[o + 128];
    __syncthreads();
    float e = cb[o];
    for (int c = 0; c < 256; c++) e += ds[c] * cw[o * 256 + c];
    float s = e, q = e * e;
    blockReduce2(s, q, sh);
    float mu = s * (1.f / 128.f);
    float rstd = rsqrtf(q * (1.f / 128.f) - mu * mu + 1e-5f);
    float y = (e - mu) * rstd * naw[o] + nab[o];
    xa[((size_t)b * 16 + p) * 128 + o] = gelu_f(y);
}

__global__ void k_kv(const float* __restrict__ xa, const float* __restrict__ kw,
                     const float* __restrict__ vw, float* __restrict__ kk, float* __restrict__ vt) {
    int p = blockIdx.x, b = blockIdx.y, t = threadIdx.x;
    __shared__ float xs[128];
    if (t < 128) xs[t] = xa[((size_t)b * 16 + p) * 128 + t];
    __syncthreads();
    if (t < 128) {
        float a = 0.f;
        for (int c = 0; c < 128; c++) a += xs[c] * kw[c * 128 + t];
        kk[((size_t)b * 16 + p) * 128 + t] = a;
    }
    float a2 = 0.f;
    for (int c = 0; c < 128; c++) a2 += xs[c] * vw[c * 256 + t];
    vt[((size_t)b * 16 + p) * 256 + t] = a2;
}

__global__ void k_cpe(const float* __restrict__ vt, const float* __restrict__ cw,
                      const float* __restrict__ cb, float* __restrict__ v2) {
    int p = blockIdx.x, b = blockIdx.y, ch = threadIdx.x;
    int i = p >> 2, j = p & 3;
    float acc = cb[ch];
#pragma unroll
    for (int a = 0; a < 3; a++) {
        int ii = i + a - 1;
        if (ii < 0 || ii >= 4) continue;
#pragma unroll
        for (int d = 0; d < 3; d++) {
            int jj = j + d - 1;
            if (jj < 0 || jj >= 4) continue;
            acc += vt[((size_t)b * 16 + ii * 4 + jj) * 256 + ch] * cw[ch * 9 + a * 3 + d];
        }
    }
    v2[((size_t)b * 16 + p) * 256 + ch] = vt[((size_t)b * 16 + p) * 256 + ch] + acc;
}

// ---------------- fused attention (bf16 q in, bf16 out) ----------------
__global__ void k_attn(const __nv_bfloat16* __restrict__ q, const float* __restrict__ kk,
                       const float* __restrict__ v2, __nv_bfloat16* __restrict__ ao) {
    __shared__ float ks[8 * 260];
    __shared__ float vs[8 * 516];
    int b = blockIdx.y;
    int tid = threadIdx.x;
    for (int idx = tid; idx < 2048; idx += 256) {
        int head = idx >> 8, r = idx & 255, m = r >> 4, i = r & 15;
        ks[head * 260 + m * 16 + i] = kk[((size_t)b * 16 + m) * 128 + head * 16 + i];
    }
    for (int idx = tid; idx < 4096; idx += 256) {
        int head = idx >> 9, r = idx & 511, m = r >> 5, d = r & 31;
        vs[head * 516 + m * 32 + d] = v2[((size_t)b * 16 + m) * 256 + head * 32 + d];
    }
    __syncthreads();
    int nl = tid >> 3, head = tid & 7;
    int n = blockIdx.x * 32 + nl;
    const __nv_bfloat16* qp = q + ((size_t)b * Nq + n) * 128 + head * 16;
    float qr[16];
#pragma unroll
    for (int i = 0; i < 16; i++) qr[i] = __bfloat162float(qp[i]);
    const float* kh = ks + head * 260;
    float s[16];
    float mx = -1e30f;
#pragma unroll
    for (int m = 0; m < 16; m++) {
        float a = 0.f;
#pragma unroll
        for (int i = 0; i < 16; i++) a += qr[i] * kh[m * 16 + i];
        a *= 0.25f;
        s[m] = a;
        mx = fmaxf(mx, a);
    }
    float sum = 0.f;
#pragma unroll
    for (int m = 0; m < 16; m++) { s[m] = __expf(s[m] - mx); sum += s[m]; }
    float inv = 1.f / sum;
    float o[32];
#pragma unroll
    for (int d = 0; d < 32; d++) o[d] = 0.f;
    const float* vh = vs + head * 516;
#pragma unroll
    for (int m = 0; m < 16; m++) {
        float pm = s[m] * inv;
#pragma unroll
        for (int d = 0; d < 32; d++) o[d] += pm * vh[m * 32 + d];
    }
    __nv_bfloat16* op = ao + ((size_t)b * Nq + n) * 256 + head * 32;
#pragma unroll
    for (int d = 0; d < 32; d++) op[d] = f2b(o[d]);
}

// ---------------- LayerNorm f32 in -> bf16 out, D=256 ----------------
__global__ void k_ln(const float* __restrict__ in, const float* __restrict__ w,
                     const float* __restrict__ b, __nv_bfloat16* __restrict__ out, float eps) {
    size_t row = blockIdx.x;
    const float* ip = in + row * 256;
    float x = ip[threadIdx.x];
    float s = x, q = x * x;
    __shared__ float sh[64];
    blockReduce2(s, q, sh);
    float mu = s * (1.f / 256.f);
    float rstd = rsqrtf(q * (1.f / 256.f) - mu * mu + eps);
    out[row * 256 + threadIdx.x] = f2b((x - mu) * rstd * w[threadIdx.x] + b[threadIdx.x]);
}

// ---------------- LayerNorm bf16 in -> bf16 out, D=512 (vectorized bf162) ----------------
__global__ void k_lnb(const __nv_bfloat16* __restrict__ in, const float* __restrict__ w,
                      const float* __restrict__ b, __nv_bfloat16* __restrict__ out, float eps) {
    size_t row = blockIdx.x;
    const __nv_bfloat162* ip = (const __nv_bfloat162*)(in + row * 512);
    __nv_bfloat162 v = ip[threadIdx.x];
    float v0 = __bfloat162float(v.x), v1 = __bfloat162float(v.y);
    float s = v0 + v1, q = v0 * v0 + v1 * v1;
    __shared__ float sh[64];
    blockReduce2(s, q, sh);
    float mu = s * (1.f / 512.f);
    float rstd = rsqrtf(q * (1.f / 512.f) - mu * mu + eps);
    int c0 = threadIdx.x * 2;
    __nv_bfloat162 o;
    o.x = f2b((v0 - mu) * rstd * w[c0] + b[c0]);
    o.y = f2b((v1 - mu) * rstd * w[c0 + 1] + b[c0 + 1]);
    ((__nv_bfloat162*)(out + row * 512))[threadIdx.x] = o;
}

// ---------------- depthwise 3x3 gate conv + multiply (bf162-vectorized) ----------------
__global__ void k_gconv(const __nv_bfloat16* __restrict__ x2, const __nv_bfloat16* __restrict__ x1,
                        const float* __restrict__ gcw, const float* __restrict__ gcb,
                        __nv_bfloat16* __restrict__ gated) {
    int n = blockIdx.x, b = blockIdx.y;
    int hh = n >> 6, ww = n & 63;
    int ch = threadIdx.x * 2;
    const __nv_bfloat16* xb = x2 + (size_t)b * Nq * 512 + ch;
    float a0 = gcb[ch], a1 = gcb[ch + 1];
#pragma unroll
    for (int a = 0; a < 3; a++) {
        int hi = hh + a - 1;
        if (hi < 0 || hi >= 64) continue;
#pragma unroll
        for (int d = 0; d < 3; d++) {
            int wi = ww + d - 1;
            if (wi < 0 || wi >= 64) continue;
            __nv_bfloat162 v = *(const __nv_bfloat162*)(xb + (size_t)(hi * 64 + wi) * 512);
            a0 += __bfloat162float(v.x) * gcw[ch * 9 + a * 3 + d];
            a1 += __bfloat162float(v.y) * gcw[(ch + 1) * 9 + a * 3 + d];
        }
    }
    __nv_bfloat162 g1 = *(const __nv_bfloat162*)(x1 + ((size_t)b * Nq + n) * 512 + ch);
    __nv_bfloat162 o;
    o.x = f2b(__bfloat162float(g1.x) * a0);
    o.y = f2b(__bfloat162float(g1.y) * a1);
    *(__nv_bfloat162*)(gated + ((size_t)b * Nq + n) * 512 + ch) = o;
}

// ---------------- host launch ----------------
extern "C" void kernel_launch(void* const* d_in, const int* in_sizes, int n_in,
                              void* d_out, int out_size) {
    const float* x          = (const float*)d_in[0];
    const float* sda_conv_w = (const float*)d_in[1];
    const float* sda_gn_w   = (const float*)d_in[2];
    const float* sda_gn_b   = (const float*)d_in[3];
    const float* norm1_w    = (const float*)d_in[4];
    const float* norm1_b    = (const float*)d_in[5];
    const float* red_w      = (const float*)d_in[6];
    const float* red_b      = (const float*)d_in[7];
    const float* dw_w       = (const float*)d_in[8];
    const float* dw_b       = (const float*)d_in[9];
    const float* conv_w     = (const float*)d_in[10];
    const float* conv_b     = (const float*)d_in[11];
    const float* na_w       = (const float*)d_in[12];
    const float* na_b       = (const float*)d_in[13];
    const float* q_w        = (const float*)d_in[14];
    const float* k_w        = (const float*)d_in[15];
    const float* v_w        = (const float*)d_in[16];
    const float* cpe_w      = (const float*)d_in[17];
    const float* cpe_b      = (const float*)d_in[18];
    const float* proj_w     = (const float*)d_in[19];
    const float* proj_b     = (const float*)d_in[20];
    const float* norm2_w    = (const float*)d_in[21];
    const float* norm2_b    = (const float*)d_in[22];
    const float* fc1_w      = (const float*)d_in[23];
    const float* fc1_b      = (const float*)d_in[24];
    const float* gnorm_w    = (const float*)d_in[25];
    const float* gnorm_b    = (const float*)d_in[26];
    const float* gconv_w    = (const float*)d_in[27];
    const float* gconv_b    = (const float*)d_in[28];
    const float* fc2_w      = (const float*)d_in[29];
    const float* fc2_b      = (const float*)d_in[30];

    float* S;
    cudaGetSymbolAddress((void**)&S, g_s);
    float* mh   = S + OFF_MH;
    float* mw   = S + OFF_MW;
    float* gh   = S + OFF_GH;
    float* gw   = S + OFF_GW;
    float* res1 = S + OFF_RES1;
    __nv_bfloat16* lnb  = (__nv_bfloat16*)(S + OFF_LNB);
    __nv_bfloat16* qb   = (__nv_bfloat16*)(S + OFF_QB);
    float* r1   = S + OFF_R1;
    float* r2   = S + OFF_R2;
    float* dd   = S + OFF_D;
    float* xa   = S + OFF_XA;
    float* kk   = S + OFF_K;
    float* vt   = S + OFF_VT;
    float* v2   = S + OFF_V2;
    __nv_bfloat16* aob  = (__nv_bfloat16*)(S + OFF_AOB);
    float* t2   = S + OFF_T2;
    __nv_bfloat16* ln2b = (__nv_bfloat16*)(S + OFF_LN2B);
    __nv_bfloat16* x1b  = (__nv_bfloat16*)(S + OFF_X1B);
    __nv_bfloat16* x2b  = (__nv_bfloat16*)(S + OFF_X2B);
    __nv_bfloat16* x2ln = (__nv_bfloat16*)(S + OFF_X2LN);
    __nv_bfloat16* gtb  = (__nv_bfloat16*)(S + OFF_GTB);
    __nv_bfloat16* wtq  = (__nv_bfloat16*)(S + OFF_WTQ);
    __nv_bfloat16* wtp  = (__nv_bfloat16*)(S + OFF_WTP);
    __nv_bfloat16* wt1  = (__nv_bfloat16*)(S + OFF_WT1);
    __nv_bfloat16* wt2  = (__nv_bfloat16*)(S + OFF_WT2);

    cudaFuncSetAttribute(k_bf_gemm<32, 256>, cudaFuncAttributeMaxDynamicSharedMemorySize, DSMB);
    cudaFuncSetAttribute(k_bf_gemm<5, 256>,  cudaFuncAttributeMaxDynamicSharedMemorySize, DSMB);
    cudaFuncSetAttribute(k_bf_gemm<11, 256>, cudaFuncAttributeMaxDynamicSharedMemorySize, DSMB);
    cudaFuncSetAttribute(k_bf_gemm<21, 512>, cudaFuncAttributeMaxDynamicSharedMemorySize, DSMB);

    // weight transposes -> bf16 K-major (single merged launch)
    k_wt_all<<<480, dim3(32, 8)>>>(q_w, proj_w, fc1_w, fc2_w, wtq, wtp, wt1, wt2);

    // SDAM
    k_mean<<<Bq * Cq, 64>>>(x, mh, mw);
    k_sdagn<<<dim3(16, Bq, 2), 256>>>(mh, mw, sda_conv_w, sda_gn_w, sda_gn_b, gh, gw);
    k_tokens<<<dim3(128, Bq), dim3(32, 8)>>>(x, gh, gw, norm1_w, norm1_b, res1, lnb);

    // reduced path
    k_red1<<<dim3(256, Bq), 256>>>(lnb, red_w, red_b, r1);
    k_red2<<<dim3(16, Bq), 256>>>(r1, red_w, red_b, r2);
    k_dw3<<<dim3(16, Bq), 256>>>(r2, dw_w, dw_b, dd);
    k_na<<<dim3(16, Bq), 128>>>(dd, conv_w, conv_b, na_w, na_b, xa);
    k_kv<<<dim3(16, Bq), 256>>>(xa, k_w, v_w, kk, vt);
    k_cpe<<<dim3(16, Bq), 256>>>(vt, cpe_w, cpe_b, v2);

    // q projection -> bf16 (M, 128, K=256)
    k_bf_gemm<32, 256><<<dim3(1, Mrows / 128), 256, DSMB>>>(lnb, wtq, nullptr, nullptr, qb, nullptr, Mrows, 128);

    // attention
    k_attn<<<dim3(128, Bq), 256>>>(qb, kk, v2, aob);

    // proj + bias + residual -> f32 t2
    k_bf_gemm<5, 256><<<dim3(2, Mrows / 128), 256, DSMB>>>(aob, wtp, proj_b, res1, t2, nullptr, Mrows, 256);

    // MLP
    k_ln<<<Mrows, 256>>>(t2, norm2_w, norm2_b, ln2b, 1e-6f);
    k_bf_gemm<11, 256><<<dim3(8, Mrows / 128), 256, DSMB>>>(ln2b, wt1, fc1_b, nullptr, x1b, x2b, Mrows, 1024);
    k_lnb<<<Mrows, 256>>>(x2b, gnorm_w, gnorm_b, x2ln, 1e-5f);
    k_gconv<<<dim3(4096, Bq), 256>>>(x2ln, x1b, gconv_w, gconv_b, gtb);
    // fc2 + bias + residual, fused transpose -> d_out [B,C,H,W]
    k_bf_gemm<21, 512><<<dim3(2, Mrows / 128), 256, DSMB>>>(gtb, wt2, fc2_b, t2, d_out, nullptr, Mrows, 256);
}

// round 13
// speedup vs baseline: 1.1366x; 1.1366x over previous
#include <cuda_runtime.h>
#include <cuda_bf16.h>
#include <math.h>
#include <stdint.h>
#include <mma.h>

using namespace nvcuda;

// ---------------- problem constants ----------------
#define Bq 16
#define Cq 256
#define Hq 64
#define Wq 64
#define Nq 4096
#define NHq 8
#define CRq 128
#define HIDq 1024
#define HALFq 512
#define Mrows (Bq*Nq)      // 65536

// ---------------- scratch layout (float units) ----------------
#define OFF_MH    0ull
#define OFF_MW    262144ull
#define OFF_GH    524288ull
#define OFF_GW    786432ull
#define OFF_RES1  1048576ull      // f32  [M,256]
#define OFF_LNB   17825792ull     // bf16 [M,256]
#define OFF_QB    26214400ull     // bf16 [M,128]
#define OFF_R1    30408704ull     // f32  [B,256,256]
#define OFF_R2    31457280ull     // f32  [B,16,256]
#define OFF_D     31522816ull     // f32  [B,16,256]
#define OFF_XA    31588352ull     // f32  [B,16,128]
#define OFF_K     31621120ull     // f32  [B,16,128]
#define OFF_VT    31653888ull     // f32  [B,16,256]
#define OFF_V2    31719424ull     // f32  [B,16,256]
#define OFF_AOB   31784960ull     // bf16 [M,256]
#define OFF_T2    40173568ull     // f32  [M,256]
#define OFF_LN2B  56950784ull     // bf16 [M,256]
#define OFF_X1B   65339392ull     // bf16 [M,512]
#define OFF_X2B   82116608ull     // bf16 [M,512]
#define OFF_X2LN  98893824ull     // bf16 [M,512]
#define OFF_GTB   115671040ull    // bf16 [M,512]
#define OFF_WTQ   132448256ull    // bf16 [128,256]
#define OFF_WTP   132464640ull    // bf16 [256,256]
#define OFF_WT1   132497408ull    // bf16 [1024,256]
#define OFF_WT2   132628480ull    // bf16 [256,512]
#define G_TOTAL   132694016ull

static __device__ float g_s[G_TOTAL];

#define DINL __device__ __forceinline__

DINL float gelu_f(float x) { return 0.5f * x * (1.0f + erff(x * 0.70710678118654752f)); }
DINL __nv_bfloat16 f2b(float x) { return __float2bfloat16_rn(x); }

DINL void blockReduce2(float& s, float& q, float* sh) {
    int lane = threadIdx.x & 31, wid = threadIdx.x >> 5;
#pragma unroll
    for (int o = 16; o > 0; o >>= 1) {
        s += __shfl_down_sync(0xffffffffu, s, o);
        q += __shfl_down_sync(0xffffffffu, q, o);
    }
    if (lane == 0) { sh[wid] = s; sh[32 + wid] = q; }
    __syncthreads();
    if (threadIdx.x == 0) {
        float ss = 0.f, qq = 0.f;
        int nw = blockDim.x >> 5;
        for (int i = 0; i < nw; i++) { ss += sh[i]; qq += sh[32 + i]; }
        sh[0] = ss; sh[32] = qq;
    }
    __syncthreads();
    s = sh[0]; q = sh[32];
}

// ================= wmma bf16 GEMM, 4-stage pipeline (R11-proven, runtime K) =================
// C = A[M,K] @ BT[N,K]^T. OP bits: 1 bias, 2 gelu, 4 residual,
// 8 split-bf16 (fc1), 16 transposed f32 (fc2 -> [B,C,HW]), 32 plain bf16 (q).
// CTA 128x128, K-chunk 32, 256 threads (8 warps 2x4, 64x32 each), 4-stage cp.async.
#define KC 32
#define LDE 40                       // bf16 elems per smem row (32 data + 8 pad = 80B)
#define STG_E (256*LDE)              // elems per stage = 10240
#define NSTG 4
#define DSMB (NSTG*STG_E*2)          // 81920 bytes

template <int OP>
__global__ __launch_bounds__(256) void k_bf_gemm(const __nv_bfloat16* __restrict__ A,
        const __nv_bfloat16* __restrict__ BT, const float* __restrict__ bias,
        const float* __restrict__ res, void* __restrict__ Cv, void* __restrict__ C2v,
        int M, int N, int K) {
    extern __shared__ __align__(16) char dsm[];
    __nv_bfloat16* sm = (__nv_bfloat16*)dsm;
    __shared__ float sbias[128];
    int tid = threadIdx.x;
    int m0 = blockIdx.y << 7, n0 = blockIdx.x << 7;
    if ((OP & 1) && tid < 128) sbias[tid] = bias[n0 + tid];

    int w = tid >> 5;
    int wm = w >> 2, wn = w & 3;     // 2x4 warps: 64-row x 32-col tiles

    wmma::fragment<wmma::accumulator, 16, 16, 16, float> acc[4][2];
#pragma unroll
    for (int mi = 0; mi < 4; mi++)
#pragma unroll
        for (int ni = 0; ni < 2; ni++) wmma::fill_fragment(acc[mi][ni], 0.f);

    int seg = tid & 3, r0 = tid >> 2;
    const __nv_bfloat16* Ag = A + (size_t)(m0 + r0) * K + seg * 8;
    const __nv_bfloat16* Bg = BT + (size_t)(n0 + r0) * K + seg * 8;
    uint32_t sbase = (uint32_t)__cvta_generic_to_shared(sm);
    int nk = K >> 5;

#define ISSUE_CHUNK(i)                                                               \
    {                                                                                \
        uint32_t ba = sbase + (uint32_t)(((i) & 3) * (STG_E * 2))                    \
                    + (uint32_t)(r0 * 80 + seg * 16);                                \
        const __nv_bfloat16* ga = Ag + (i) * KC;                                     \
        const __nv_bfloat16* gb = Bg + (i) * KC;                                     \
        _Pragma("unroll")                                                            \
        for (int it = 0; it < 2; it++)                                               \
            asm volatile("cp.async.cg.shared.global [%0], [%1], 16;"                 \
                :: "r"(ba + it * (64u * 80u)), "l"(ga + (size_t)it * 64 * K)         \
                : "memory");                                                         \
        _Pragma("unroll")                                                            \
        for (int it = 0; it < 2; it++)                                               \
            asm volatile("cp.async.cg.shared.global [%0], [%1], 16;"                 \
                :: "r"(ba + 10240u + it * (64u * 80u)), "l"(gb + (size_t)it * 64 * K)\
                : "memory");                                                         \
        asm volatile("cp.async.commit_group;");                                      \
    }

    ISSUE_CHUNK(0); ISSUE_CHUNK(1); ISSUE_CHUNK(2);
    for (int i = 0; i < nk; i++) {
        asm volatile("cp.async.wait_group 2;");
        __syncthreads();
        if (i + 3 < nk) { ISSUE_CHUNK(i + 3); }
        else { asm volatile("cp.async.commit_group;"); }
        const __nv_bfloat16* As = sm + (i & 3) * STG_E;
        const __nv_bfloat16* Bs = As + 128 * LDE;
#pragma unroll
        for (int kk = 0; kk < KC; kk += 16) {
            wmma::fragment<wmma::matrix_a, 16, 16, 16, __nv_bfloat16, wmma::row_major> af[4];
            wmma::fragment<wmma::matrix_b, 16, 16, 16, __nv_bfloat16, wmma::col_major> bf[2];
#pragma unroll
            for (int mi = 0; mi < 4; mi++)
                wmma::load_matrix_sync(af[mi], As + (wm * 64 + mi * 16) * LDE + kk, LDE);
#pragma unroll
            for (int ni = 0; ni < 2; ni++)
                wmma::load_matrix_sync(bf[ni], Bs + (wn * 32 + ni * 16) * LDE + kk, LDE);
#pragma unroll
            for (int mi = 0; mi < 4; mi++)
#pragma unroll
                for (int ni = 0; ni < 2; ni++)
                    wmma::mma_sync(acc[mi][ni], af[mi], bf[ni], acc[mi][ni]);
        }
    }
    __syncthreads();

    float* Cs = (float*)dsm;
#pragma unroll
    for (int mi = 0; mi < 4; mi++)
#pragma unroll
        for (int ni = 0; ni < 2; ni++)
            wmma::store_matrix_sync(Cs + (wm * 64 + mi * 16) * 132 + wn * 32 + ni * 16,
                                    acc[mi][ni], 132, wmma::mem_row_major);
    __syncthreads();

    int col = tid & 127, rr = tid >> 7;
    if (OP & 8) {
        __nv_bfloat16* dst = (n0 < 512) ? (__nv_bfloat16*)Cv : (__nv_bfloat16*)C2v;
        int nloc = n0 & 511;
#pragma unroll 4
        for (int r = rr; r < 128; r += 2) {
            float v = Cs[r * 132 + col] + sbias[col];
            dst[(size_t)(m0 + r) * 512 + nloc + col] = f2b(gelu_f(v));
        }
    } else if (OP & 16) {
        const float* Rp = res + (size_t)m0 * N + n0 + col;
#pragma unroll 4
        for (int r = rr; r < 128; r += 2) {
            float v = Cs[r * 132 + col] + sbias[col] + Rp[(size_t)r * N];
            Cs[r * 132 + col] = v;
        }
        __syncthreads();
        int b = m0 >> 12, pix0 = m0 & 4095;
        float* outp = (float*)Cv + (size_t)b * Cq * Nq + pix0;
        int ch = tid >> 7;
        int m = tid & 127;
#pragma unroll 4
        for (int cc = 0; cc < 64; cc++) {
            int c = cc * 2 + ch;
            outp[(size_t)(n0 + c) * Nq + m] = Cs[m * 132 + c];
        }
    } else if (OP & 32) {
        __nv_bfloat16* dst = (__nv_bfloat16*)Cv;
#pragma unroll 4
        for (int r = rr; r < 128; r += 2)
            dst[(size_t)(m0 + r) * N + n0 + col] = f2b(Cs[r * 132 + col]);
    } else {
        float* Cp = (float*)Cv + (size_t)m0 * N + n0 + col;
        const float* Rp = res + (size_t)m0 * N + n0 + col;
#pragma unroll 4
        for (int r = rr; r < 128; r += 2) {
            float v = Cs[r * 132 + col];
            if (OP & 1) v += sbias[col];
            if (OP & 2) v = gelu_f(v);
            if (OP & 4) v += Rp[(size_t)r * N];
            Cp[(size_t)r * N] = v;
        }
    }
}

// ---------------- merged weight transposes: all 4 in one launch ----------------
__global__ void k_wt_all(const float* __restrict__ qw, const float* __restrict__ pw,
                         const float* __restrict__ f1w, const float* __restrict__ f2w,
                         __nv_bfloat16* __restrict__ wtq, __nv_bfloat16* __restrict__ wtp,
                         __nv_bfloat16* __restrict__ wt1, __nv_bfloat16* __restrict__ wt2) {
    __shared__ float t[32][33];
    int bid = blockIdx.x;
    const float* w; __nv_bfloat16* wt; int K, N, bx, by;
    if (bid < 32)        { w = qw;  wt = wtq; K = 256; N = 128;  int l = bid;       bx = l & 3;  by = l >> 2; }
    else if (bid < 96)   { w = pw;  wt = wtp; K = 256; N = 256;  int l = bid - 32;  bx = l & 7;  by = l >> 3; }
    else if (bid < 352)  { w = f1w; wt = wt1; K = 256; N = 1024; int l = bid - 96;  bx = l & 31; by = l >> 5; }
    else                 { w = f2w; wt = wt2; K = 512; N = 256;  int l = bid - 352; bx = l & 7;  by = l >> 3; }
    int nb = bx * 32, kb = by * 32;
    int tx = threadIdx.x, ty = threadIdx.y;
#pragma unroll
    for (int j = 0; j < 4; j++)
        t[ty + j * 8][tx] = w[(size_t)(kb + ty + j * 8) * N + nb + tx];
    __syncthreads();
#pragma unroll
    for (int j = 0; j < 4; j++)
        wt[(size_t)(nb + ty + j * 8) * K + kb + tx] = f2b(t[tx][ty + j * 8]);
}

// ---------------- K1: coordinate pooled means ----------------
__global__ void k_mean(const float* __restrict__ x, float* __restrict__ mh, float* __restrict__ mw) {
    int bc = blockIdx.x;
    const float* p = x + (size_t)bc * 4096;
    int w = threadIdx.x;
    __shared__ float part[128];
    float colsum = 0.f;
    for (int r = 0; r < 64; r++) {
        float v = p[r * 64 + w];
        colsum += v;
        float s = v;
#pragma unroll
        for (int o = 16; o > 0; o >>= 1) s += __shfl_down_sync(0xffffffffu, s, o);
        if ((w & 31) == 0) part[(w >> 5) * 64 + r] = s;
    }
    __syncthreads();
    mh[(size_t)bc * 64 + w] = (part[w] + part[64 + w]) * (1.f / 64.f);
    mw[(size_t)bc * 64 + w] = colsum * (1.f / 64.f);
}

// ---------------- K2: dwconv1d(k=7) + GroupNorm(16) + ReLU ----------------
__global__ void k_sdagn(const float* __restrict__ mh, const float* __restrict__ mw,
                        const float* __restrict__ w7, const float* __restrict__ gnw,
                        const float* __restrict__ gnb, float* __restrict__ gh, float* __restrict__ gw_) {
    int grp = blockIdx.x, b = blockIdx.y;
    const float* mean = (blockIdx.z ? mw : mh) + (size_t)b * Cq * 64;
    float* out = (blockIdx.z ? gw_ : gh) + (size_t)b * Cq * 64;
    __shared__ float buf[1024];
    __shared__ float sh[64];
    int tid = threadIdx.x;
    float ls = 0.f, lq = 0.f;
#pragma unroll
    for (int j = 0; j < 4; j++) {
        int idx = tid + j * 256;
        int c = grp * 16 + (idx >> 6), l = idx & 63;
        const float* m = mean + c * 64;
        float acc = 0.f;
#pragma unroll
        for (int k = 0; k < 7; k++) {
            int ll = l + k - 3;
            if (ll >= 0 && ll < 64) acc += m[ll] * w7[c * 7 + k];
        }
        buf[idx] = acc; ls += acc; lq += acc * acc;
    }
    blockReduce2(ls, lq, sh);
    float mu = ls * (1.f / 1024.f);
    float rstd = rsqrtf(lq * (1.f / 1024.f) - mu * mu + 1e-5f);
#pragma unroll
    for (int j = 0; j < 4; j++) {
        int idx = tid + j * 256;
        int c = grp * 16 + (idx >> 6), l = idx & 63;
        float y = (buf[idx] - mu) * rstd * gnw[c] + gnb[c];
        out[(size_t)c * 64 + l] = fmaxf(y, 0.f);
    }
}

// ---------------- K3: modulate + to tokens + LN1 ----------------
__global__ void k_tokens(const float* __restrict__ x, const float* __restrict__ gh,
                         const float* __restrict__ gw_, const float* __restrict__ n1w,
                         const float* __restrict__ n1b, float* __restrict__ res,
                         __nv_bfloat16* __restrict__ ln) {
    int b = blockIdx.y;
    int n0 = blockIdx.x * 32;
    int h = n0 >> 6, w0 = n0 & 63;
    int nx = threadIdx.x, cy = threadIdx.y;
    __shared__ float tile[256][33];
    __shared__ float mu[32], rs[32];
    const float* ghb = gh + (size_t)b * Cq * 64;
    const float* gwb = gw_ + (size_t)b * Cq * 64;
    const float* xb = x + (size_t)b * Cq * Nq;
#pragma unroll 4
    for (int j = 0; j < 32; j++) {
        int c = cy * 32 + j;
        float v = xb[(size_t)c * Nq + h * 64 + w0 + nx] * ghb[c * 64 + h] * gwb[c * 64 + w0 + nx];
        tile[c][nx] = v;
    }
    __syncthreads();
    int tid = cy * 32 + nx, lane = tid & 31, warp = tid >> 5;
    for (int nn = warp; nn < 32; nn += 8) {
        float s = 0.f, q = 0.f;
        for (int c = lane; c < 256; c += 32) { float v = tile[c][nn]; s += v; q += v * v; }
#pragma unroll
        for (int o = 16; o > 0; o >>= 1) {
            s += __shfl_down_sync(0xffffffffu, s, o);
            q += __shfl_down_sync(0xffffffffu, q, o);
        }
        if (lane == 0) {
            float m = s * (1.f / 256.f);
            mu[nn] = m; rs[nn] = rsqrtf(q * (1.f / 256.f) - m * m + 1e-6f);
        }
    }
    __syncthreads();
    float* resp = res + ((size_t)b * Nq + n0) * Cq;
    __nv_bfloat16* lnp = ln + ((size_t)b * Nq + n0) * Cq;
    for (int idx = tid; idx < 32 * 256; idx += 256) {
        int nl = idx >> 8, c = idx & 255;
        float v = tile[c][nl];
        resp[(size_t)nl * 256 + c] = v;
        lnp[(size_t)nl * 256 + c] = f2b((v - mu[nl]) * rs[nl] * n1w[c] + n1b[c]);
    }
}

// ---------------- reduction path (separate kernels — R8-proven) ----------------
__global__ void k_red1(const __nv_bfloat16* __restrict__ ln1, const float* __restrict__ rw,
                       const float* __restrict__ rb, float* __restrict__ r1) {
    int p = blockIdx.x, b = blockIdx.y, c = threadIdx.x;
    int i = p >> 4, j = p & 15;
    float acc = rb[c];
    const __nv_bfloat16* base = ln1 + (size_t)b * Nq * Cq + c;
#pragma unroll
    for (int a = 0; a < 4; a++)
#pragma unroll
        for (int d = 0; d < 4; d++) {
            int n = (4 * i + a) * 64 + 4 * j + d;
            acc += __bfloat162float(base[(size_t)n * 256]) * rw[c * 16 + a * 4 + d];
        }
    r1[((size_t)b * 256 + p) * 256 + c] = acc;
}

__global__ void k_red2(const float* __restrict__ r1, const float* __restrict__ rw,
                       const float* __restrict__ rb, float* __restrict__ r2) {
    int p2 = blockIdx.x, b = blockIdx.y, c = threadIdx.x;
    int i2 = p2 >> 2, j2 = p2 & 3;
    float acc = rb[c];
#pragma unroll
    for (int a = 0; a < 4; a++)
#pragma unroll
        for (int d = 0; d < 4; d++) {
            int p = (4 * i2 + a) * 16 + (4 * j2 + d);
            acc += r1[((size_t)b * 256 + p) * 256 + c] * rw[c * 16 + a * 4 + d];
        }
    r2[((size_t)b * 16 + p2) * 256 + c] = acc;
}

__global__ void k_dw3(const float* __restrict__ r2, const float* __restrict__ dww,
                      const float* __restrict__ dwb, float* __restrict__ dd) {
    int p = blockIdx.x, b = blockIdx.y, c = threadIdx.x;
    int i = p >> 2, j = p & 3;
    float acc = dwb[c];
#pragma unroll
    for (int a = 0; a < 3; a++) {
        int ii = i + a - 1;
        if (ii < 0 || ii >= 4) continue;
#pragma unroll
        for (int d = 0; d < 3; d++) {
            int jj = j + d - 1;
            if (jj < 0 || jj >= 4) continue;
            acc += r2[((size_t)b * 16 + ii * 4 + jj) * 256 + c] * dww[c * 9 + a * 3 + d];
        }
    }
    dd[((size_t)b * 16 + p) * 256 + c] = acc;
}

__global__ void k_na(const float* __restrict__ dd, const float* __restrict__ cw,
                     const float* __restrict__ cb, const float* __restrict__ naw,
                     const float* __restrict__ nab, float* __restrict__ xa) {
    int p = blockIdx.x, b = blockIdx.y, o = threadIdx.x;
    __shared__ float ds[256];
    __shared__ float sh[64];
    const float* dp = dd + ((size_t)b * 16 + p) * 256;
    ds[o] = dp[o]; ds[o + 128] = dp[o + 128];
    __syncthreads();
    float e = cb[o];
    for (int c = 0; c < 256; c++) e += ds[c] * cw[o * 256 + c];
    float s = e, q = e * e;
    blockReduce2(s, q, sh);
    float mu = s * (1.f / 128.f);
    float rstd = rsqrtf(q * (1.f / 128.f) - mu * mu + 1e-5f);
    float y = (e - mu) * rstd * naw[o] + nab[o];
    xa[((size_t)b * 16 + p) * 128 + o] = gelu_f(y);
}

__global__ void k_kv(const float* __restrict__ xa, const float* __restrict__ kw,
                     const float* __restrict__ vw, float* __restrict__ kk, float* __restrict__ vt) {
    int p = blockIdx.x, b = blockIdx.y, t = threadIdx.x;
    __shared__ float xs[128];
    if (t < 128) xs[t] = xa[((size_t)b * 16 + p) * 128 + t];
    __syncthreads();
    if (t < 128) {
        float a = 0.f;
        for (int c = 0; c < 128; c++) a += xs[c] * kw[c * 128 + t];
        kk[((size_t)b * 16 + p) * 128 + t] = a;
    }
    float a2 = 0.f;
    for (int c = 0; c < 128; c++) a2 += xs[c] * vw[c * 256 + t];
    vt[((size_t)b * 16 + p) * 256 + t] = a2;
}

__global__ void k_cpe(const float* __restrict__ vt, const float* __restrict__ cw,
                      const float* __restrict__ cb, float* __restrict__ v2) {
    int p = blockIdx.x, b = blockIdx.y, ch = threadIdx.x;
    int i = p >> 2, j = p & 3;
    float acc = cb[ch];
#pragma unroll
    for (int a = 0; a < 3; a++) {
        int ii = i + a - 1;
        if (ii < 0 || ii >= 4) continue;
#pragma unroll
        for (int d = 0; d < 3; d++) {
            int jj = j + d - 1;
            if (jj < 0 || jj >= 4) continue;
            acc += vt[((size_t)b * 16 + ii * 4 + jj) * 256 + ch] * cw[ch * 9 + a * 3 + d];
        }
    }
    v2[((size_t)b * 16 + p) * 256 + ch] = vt[((size_t)b * 16 + p) * 256 + ch] + acc;
}

// ---------------- fused attention (bf16 q in, bf16 out) ----------------
__global__ void k_attn(const __nv_bfloat16* __restrict__ q, const float* __restrict__ kk,
                       const float* __restrict__ v2, __nv_bfloat16* __restrict__ ao) {
    __shared__ float ks[8 * 260];
    __shared__ float vs[8 * 516];
    int b = blockIdx.y;
    int tid = threadIdx.x;
    for (int idx = tid; idx < 2048; idx += 256) {
        int head = idx >> 8, r = idx & 255, m = r >> 4, i = r & 15;
        ks[head * 260 + m * 16 + i] = kk[((size_t)b * 16 + m) * 128 + head * 16 + i];
    }
    for (int idx = tid; idx < 4096; idx += 256) {
        int head = idx >> 9, r = idx & 511, m = r >> 5, d = r & 31;
        vs[head * 516 + m * 32 + d] = v2[((size_t)b * 16 + m) * 256 + head * 32 + d];
    }
    __syncthreads();
    int nl = tid >> 3, head = tid & 7;
    int n = blockIdx.x * 32 + nl;
    const __nv_bfloat16* qp = q + ((size_t)b * Nq + n) * 128 + head * 16;
    float qr[16];
#pragma unroll
    for (int i = 0; i < 16; i++) qr[i] = __bfloat162float(qp[i]);
    const float* kh = ks + head * 260;
    float s[16];
    float mx = -1e30f;
#pragma unroll
    for (int m = 0; m < 16; m++) {
        float a = 0.f;
#pragma unroll
        for (int i = 0; i < 16; i++) a += qr[i] * kh[m * 16 + i];
        a *= 0.25f;
        s[m] = a;
        mx = fmaxf(mx, a);
    }
    float sum = 0.f;
#pragma unroll
    for (int m = 0; m < 16; m++) { s[m] = __expf(s[m] - mx); sum += s[m]; }
    float inv = 1.f / sum;
    float o[32];
#pragma unroll
    for (int d = 0; d < 32; d++) o[d] = 0.f;
    const float* vh = vs + head * 516;
#pragma unroll
    for (int m = 0; m < 16; m++) {
        float pm = s[m] * inv;
#pragma unroll
        for (int d = 0; d < 32; d++) o[d] += pm * vh[m * 32 + d];
    }
    __nv_bfloat16* op = ao + ((size_t)b * Nq + n) * 256 + head * 32;
#pragma unroll
    for (int d = 0; d < 32; d++) op[d] = f2b(o[d]);
}

// ---------------- LayerNorm f32 in -> bf16 out, D=256 ----------------
__global__ void k_ln(const float* __restrict__ in, const float* __restrict__ w,
                     const float* __restrict__ b, __nv_bfloat16* __restrict__ out, float eps) {
    size_t row = blockIdx.x;
    const float* ip = in + row * 256;
    float x = ip[threadIdx.x];
    float s = x, q = x * x;
    __shared__ float sh[64];
    blockReduce2(s, q, sh);
    float mu = s * (1.f / 256.f);
    float rstd = rsqrtf(q * (1.f / 256.f) - mu * mu + eps);
    out[row * 256 + threadIdx.x] = f2b((x - mu) * rstd * w[threadIdx.x] + b[threadIdx.x]);
}

// ---------------- LayerNorm bf16 in -> bf16 out, D=512 (vectorized bf162) ----------------
__global__ void k_lnb(const __nv_bfloat16* __restrict__ in, const float* __restrict__ w,
                      const float* __restrict__ b, __nv_bfloat16* __restrict__ out, float eps) {
    size_t row = blockIdx.x;
    const __nv_bfloat162* ip = (const __nv_bfloat162*)(in + row * 512);
    __nv_bfloat162 v = ip[threadIdx.x];
    float v0 = __bfloat162float(v.x), v1 = __bfloat162float(v.y);
    float s = v0 + v1, q = v0 * v0 + v1 * v1;
    __shared__ float sh[64];
    blockReduce2(s, q, sh);
    float mu = s * (1.f / 512.f);
    float rstd = rsqrtf(q * (1.f / 512.f) - mu * mu + eps);
    int c0 = threadIdx.x * 2;
    __nv_bfloat162 o;
    o.x = f2b((v0 - mu) * rstd * w[c0] + b[c0]);
    o.y = f2b((v1 - mu) * rstd * w[c0 + 1] + b[c0 + 1]);
    ((__nv_bfloat162*)(out + row * 512))[threadIdx.x] = o;
}

// ---------------- depthwise 3x3 gate conv + multiply (bf162-vectorized) ----------------
__global__ void k_gconv(const __nv_bfloat16* __restrict__ x2, const __nv_bfloat16* __restrict__ x1,
                        const float* __restrict__ gcw, const float* __restrict__ gcb,
                        __nv_bfloat16* __restrict__ gated) {
    int n = blockIdx.x, b = blockIdx.y;
    int hh = n >> 6, ww = n & 63;
    int ch = threadIdx.x * 2;
    const __nv_bfloat16* xb = x2 + (size_t)b * Nq * 512 + ch;
    float a0 = gcb[ch], a1 = gcb[ch + 1];
#pragma unroll
    for (int a = 0; a < 3; a++) {
        int hi = hh + a - 1;
        if (hi < 0 || hi >= 64) continue;
#pragma unroll
        for (int d = 0; d < 3; d++) {
            int wi = ww + d - 1;
            if (wi < 0 || wi >= 64) continue;
            __nv_bfloat162 v = *(const __nv_bfloat162*)(xb + (size_t)(hi * 64 + wi) * 512);
            a0 += __bfloat162float(v.x) * gcw[ch * 9 + a * 3 + d];
            a1 += __bfloat162float(v.y) * gcw[(ch + 1) * 9 + a * 3 + d];
        }
    }
    __nv_bfloat162 g1 = *(const __nv_bfloat162*)(x1 + ((size_t)b * Nq + n) * 512 + ch);
    __nv_bfloat162 o;
    o.x = f2b(__bfloat162float(g1.x) * a0);
    o.y = f2b(__bfloat162float(g1.y) * a1);
    *(__nv_bfloat162*)(gated + ((size_t)b * Nq + n) * 512 + ch) = o;
}

// ---------------- host launch ----------------
extern "C" void kernel_launch(void* const* d_in, const int* in_sizes, int n_in,
                              void* d_out, int out_size) {
    const float* x          = (const float*)d_in[0];
    const float* sda_conv_w = (const float*)d_in[1];
    const float* sda_gn_w   = (const float*)d_in[2];
    const float* sda_gn_b   = (const float*)d_in[3];
    const float* norm1_w    = (const float*)d_in[4];
    const float* norm1_b    = (const float*)d_in[5];
    const float* red_w      = (const float*)d_in[6];
    const float* red_b      = (const float*)d_in[7];
    const float* dw_w       = (const float*)d_in[8];
    const float* dw_b       = (const float*)d_in[9];
    const float* conv_w     = (const float*)d_in[10];
    const float* conv_b     = (const float*)d_in[11];
    const float* na_w       = (const float*)d_in[12];
    const float* na_b       = (const float*)d_in[13];
    const float* q_w        = (const float*)d_in[14];
    const float* k_w        = (const float*)d_in[15];
    const float* v_w        = (const float*)d_in[16];
    const float* cpe_w      = (const float*)d_in[17];
    const float* cpe_b      = (const float*)d_in[18];
    const float* proj_w     = (const float*)d_in[19];
    const float* proj_b     = (const float*)d_in[20];
    const float* norm2_w    = (const float*)d_in[21];
    const float* norm2_b    = (const float*)d_in[22];
    const float* fc1_w      = (const float*)d_in[23];
    const float* fc1_b      = (const float*)d_in[24];
    const float* gnorm_w    = (const float*)d_in[25];
    const float* gnorm_b    = (const float*)d_in[26];
    const float* gconv_w    = (const float*)d_in[27];
    const float* gconv_b    = (const float*)d_in[28];
    const float* fc2_w      = (const float*)d_in[29];
    const float* fc2_b      = (const float*)d_in[30];

    float* S;
    cudaGetSymbolAddress((void**)&S, g_s);
    float* mh   = S + OFF_MH;
    float* mw   = S + OFF_MW;
    float* gh   = S + OFF_GH;
    float* gw   = S + OFF_GW;
    float* res1 = S + OFF_RES1;
    __nv_bfloat16* lnb  = (__nv_bfloat16*)(S + OFF_LNB);
    __nv_bfloat16* qb   = (__nv_bfloat16*)(S + OFF_QB);
    float* r1   = S + OFF_R1;
    float* r2   = S + OFF_R2;
    float* dd   = S + OFF_D;
    float* xa   = S + OFF_XA;
    float* kk   = S + OFF_K;
    float* vt   = S + OFF_VT;
    float* v2   = S + OFF_V2;
    __nv_bfloat16* aob  = (__nv_bfloat16*)(S + OFF_AOB);
    float* t2   = S + OFF_T2;
    __nv_bfloat16* ln2b = (__nv_bfloat16*)(S + OFF_LN2B);
    __nv_bfloat16* x1b  = (__nv_bfloat16*)(S + OFF_X1B);
    __nv_bfloat16* x2b  = (__nv_bfloat16*)(S + OFF_X2B);
    __nv_bfloat16* x2ln = (__nv_bfloat16*)(S + OFF_X2LN);
    __nv_bfloat16* gtb  = (__nv_bfloat16*)(S + OFF_GTB);
    __nv_bfloat16* wtq  = (__nv_bfloat16*)(S + OFF_WTQ);
    __nv_bfloat16* wtp  = (__nv_bfloat16*)(S + OFF_WTP);
    __nv_bfloat16* wt1  = (__nv_bfloat16*)(S + OFF_WT1);
    __nv_bfloat16* wt2  = (__nv_bfloat16*)(S + OFF_WT2);

    cudaFuncSetAttribute(k_bf_gemm<32>, cudaFuncAttributeMaxDynamicSharedMemorySize, DSMB);
    cudaFuncSetAttribute(k_bf_gemm<5>,  cudaFuncAttributeMaxDynamicSharedMemorySize, DSMB);
    cudaFuncSetAttribute(k_bf_gemm<11>, cudaFuncAttributeMaxDynamicSharedMemorySize, DSMB);
    cudaFuncSetAttribute(k_bf_gemm<21>, cudaFuncAttributeMaxDynamicSharedMemorySize, DSMB);

    // weight transposes -> bf16 K-major (single merged launch)
    k_wt_all<<<480, dim3(32, 8)>>>(q_w, proj_w, fc1_w, fc2_w, wtq, wtp, wt1, wt2);

    // SDAM
    k_mean<<<Bq * Cq, 64>>>(x, mh, mw);
    k_sdagn<<<dim3(16, Bq, 2), 256>>>(mh, mw, sda_conv_w, sda_gn_w, sda_gn_b, gh, gw);
    k_tokens<<<dim3(128, Bq), dim3(32, 8)>>>(x, gh, gw, norm1_w, norm1_b, res1, lnb);

    // reduced path
    k_red1<<<dim3(256, Bq), 256>>>(lnb, red_w, red_b, r1);
    k_red2<<<dim3(16, Bq), 256>>>(r1, red_w, red_b, r2);
    k_dw3<<<dim3(16, Bq), 256>>>(r2, dw_w, dw_b, dd);
    k_na<<<dim3(16, Bq), 128>>>(dd, conv_w, conv_b, na_w, na_b, xa);
    k_kv<<<dim3(16, Bq), 256>>>(xa, k_w, v_w, kk, vt);
    k_cpe<<<dim3(16, Bq), 256>>>(vt, cpe_w, cpe_b, v2);

    // q projection -> bf16 (M, 128, K=256)
    k_bf_gemm<32><<<dim3(1, Mrows / 128), 256, DSMB>>>(lnb, wtq, nullptr, nullptr, qb, nullptr, Mrows, 128, 256);

    // attention
    k_attn<<<dim3(128, Bq), 256>>>(qb, kk, v2, aob);

    // proj + bias + residual -> f32 t2
    k_bf_gemm<5><<<dim3(2, Mrows / 128), 256, DSMB>>>(aob, wtp, proj_b, res1, t2, nullptr, Mrows, 256, 256);

    // MLP
    k_ln<<<Mrows, 256>>>(t2, norm2_w, norm2_b, ln2b, 1e-6f);
    k_bf_gemm<11><<<dim3(8, Mrows / 128), 256, DSMB>>>(ln2b, wt1, fc1_b, nullptr, x1b, x2b, Mrows, 1024, 256);
    k_lnb<<<Mrows, 256>>>(x2b, gnorm_w, gnorm_b, x2ln, 1e-5f);
    k_gconv<<<dim3(4096, Bq), 256>>>(x2ln, x1b, gconv_w, gconv_b, gtb);
    // fc2 + bias + residual, fused transpose -> d_out [B,C,H,W]
    k_bf_gemm<21><<<dim3(2, Mrows / 128), 256, DSMB>>>(gtb, wt2, fc2_b, t2, d_out, nullptr, Mrows, 256, 512);
}

// round 14
// speedup vs baseline: 1.3436x; 1.1820x over previous
#include <cuda_runtime.h>
#include <cuda_bf16.h>
#include <math.h>
#include <stdint.h>
#include <mma.h>

using namespace nvcuda;

// ---------------- problem constants ----------------
#define Bq 16
#define Cq 256
#define Hq 64
#define Wq 64
#define Nq 4096
#define NHq 8
#define CRq 128
#define HIDq 1024
#define HALFq 512
#define Mrows (Bq*Nq)      // 65536

// ---------------- scratch layout (float units) ----------------
#define OFF_MH    0ull
#define OFF_MW    262144ull
#define OFF_GH    524288ull
#define OFF_GW    786432ull
#define OFF_RES1  1048576ull      // f32  [M,256]
#define OFF_LNB   17825792ull     // bf16 [M,256]
#define OFF_QB    26214400ull     // bf16 [M,128]
#define OFF_R1    30408704ull     // f32  [B,256,256]
#define OFF_R2    31457280ull     // f32  [B,16,256]
#define OFF_D     31522816ull     // f32  [B,16,256]
#define OFF_XA    31588352ull     // f32  [B,16,128]  (unused after na+kv fusion)
#define OFF_K     31621120ull     // f32  [B,16,128]
#define OFF_VT    31653888ull     // f32  [B,16,256]
#define OFF_V2    31719424ull     // f32  [B,16,256]
#define OFF_AOB   31784960ull     // bf16 [M,256]
#define OFF_T2    40173568ull     // f32  [M,256]
#define OFF_LN2B  56950784ull     // bf16 [M,256]
#define OFF_X1B   65339392ull     // bf16 [M,512]
#define OFF_X2B   82116608ull     // bf16 [M,512]
#define OFF_X2LN  98893824ull     // bf16 [M,512]
#define OFF_GTB   115671040ull    // bf16 [M,512]
#define OFF_WTQ   132448256ull    // bf16 [128,256]
#define OFF_WTP   132464640ull    // bf16 [256,256]
#define OFF_WT1   132497408ull    // bf16 [1024,256]
#define OFF_WT2   132628480ull    // bf16 [256,512]
#define G_TOTAL   132694016ull

static __device__ float g_s[G_TOTAL];

#define DINL __device__ __forceinline__

DINL float gelu_f(float x) { return 0.5f * x * (1.0f + erff(x * 0.70710678118654752f)); }
DINL __nv_bfloat16 f2b(float x) { return __float2bfloat16_rn(x); }
DINL unsigned pk2(float a, float b) {
    __nv_bfloat162 h; h.x = f2b(a); h.y = f2b(b);
    return *(unsigned*)&h;
}

DINL void blockReduce2(float& s, float& q, float* sh) {
    int lane = threadIdx.x & 31, wid = threadIdx.x >> 5;
#pragma unroll
    for (int o = 16; o > 0; o >>= 1) {
        s += __shfl_down_sync(0xffffffffu, s, o);
        q += __shfl_down_sync(0xffffffffu, q, o);
    }
    if (lane == 0) { sh[wid] = s; sh[32 + wid] = q; }
    __syncthreads();
    if (threadIdx.x == 0) {
        float ss = 0.f, qq = 0.f;
        int nw = blockDim.x >> 5;
        for (int i = 0; i < nw; i++) { ss += sh[i]; qq += sh[32 + i]; }
        sh[0] = ss; sh[32] = qq;
    }
    __syncthreads();
    s = sh[0]; q = sh[32];
}

// ================= wmma bf16 GEMM, 4-stage pipeline (R11-proven) =================
#define KC 32
#define LDE 40
#define STG_E (256*LDE)
#define NSTG 4
#define DSMB (NSTG*STG_E*2)          // 81920 bytes

template <int OP>
__global__ __launch_bounds__(256) void k_bf_gemm(const __nv_bfloat16* __restrict__ A,
        const __nv_bfloat16* __restrict__ BT, const float* __restrict__ bias,
        const float* __restrict__ res, void* __restrict__ Cv, void* __restrict__ C2v,
        int M, int N, int K) {
    extern __shared__ __align__(16) char dsm[];
    __nv_bfloat16* sm = (__nv_bfloat16*)dsm;
    __shared__ float sbias[128];
    int tid = threadIdx.x;
    int m0 = blockIdx.y << 7, n0 = blockIdx.x << 7;
    if ((OP & 1) && tid < 128) sbias[tid] = bias[n0 + tid];

    int w = tid >> 5;
    int wm = w >> 2, wn = w & 3;

    wmma::fragment<wmma::accumulator, 16, 16, 16, float> acc[4][2];
#pragma unroll
    for (int mi = 0; mi < 4; mi++)
#pragma unroll
        for (int ni = 0; ni < 2; ni++) wmma::fill_fragment(acc[mi][ni], 0.f);

    int seg = tid & 3, r0 = tid >> 2;
    const __nv_bfloat16* Ag = A + (size_t)(m0 + r0) * K + seg * 8;
    const __nv_bfloat16* Bg = BT + (size_t)(n0 + r0) * K + seg * 8;
    uint32_t sbase = (uint32_t)__cvta_generic_to_shared(sm);
    int nk = K >> 5;

#define ISSUE_CHUNK(i)                                                               \
    {                                                                                \
        uint32_t ba = sbase + (uint32_t)(((i) & 3) * (STG_E * 2))                    \
                    + (uint32_t)(r0 * 80 + seg * 16);                                \
        const __nv_bfloat16* ga = Ag + (i) * KC;                                     \
        const __nv_bfloat16* gb = Bg + (i) * KC;                                     \
        _Pragma("unroll")                                                            \
        for (int it = 0; it < 2; it++)                                               \
            asm volatile("cp.async.cg.shared.global [%0], [%1], 16;"                 \
                :: "r"(ba + it * (64u * 80u)), "l"(ga + (size_t)it * 64 * K)         \
                : "memory");                                                         \
        _Pragma("unroll")                                                            \
        for (int it = 0; it < 2; it++)                                               \
            asm volatile("cp.async.cg.shared.global [%0], [%1], 16;"                 \
                :: "r"(ba + 10240u + it * (64u * 80u)), "l"(gb + (size_t)it * 64 * K)\
                : "memory");                                                         \
        asm volatile("cp.async.commit_group;");                                      \
    }

    ISSUE_CHUNK(0); ISSUE_CHUNK(1); ISSUE_CHUNK(2);
    for (int i = 0; i < nk; i++) {
        asm volatile("cp.async.wait_group 2;");
        __syncthreads();
        if (i + 3 < nk) { ISSUE_CHUNK(i + 3); }
        else { asm volatile("cp.async.commit_group;"); }
        const __nv_bfloat16* As = sm + (i & 3) * STG_E;
        const __nv_bfloat16* Bs = As + 128 * LDE;
#pragma unroll
        for (int kk = 0; kk < KC; kk += 16) {
            wmma::fragment<wmma::matrix_a, 16, 16, 16, __nv_bfloat16, wmma::row_major> af[4];
            wmma::fragment<wmma::matrix_b, 16, 16, 16, __nv_bfloat16, wmma::col_major> bf[2];
#pragma unroll
            for (int mi = 0; mi < 4; mi++)
                wmma::load_matrix_sync(af[mi], As + (wm * 64 + mi * 16) * LDE + kk, LDE);
#pragma unroll
            for (int ni = 0; ni < 2; ni++)
                wmma::load_matrix_sync(bf[ni], Bs + (wn * 32 + ni * 16) * LDE + kk, LDE);
#pragma unroll
            for (int mi = 0; mi < 4; mi++)
#pragma unroll
                for (int ni = 0; ni < 2; ni++)
                    wmma::mma_sync(acc[mi][ni], af[mi], bf[ni], acc[mi][ni]);
        }
    }
    __syncthreads();

    float* Cs = (float*)dsm;
#pragma unroll
    for (int mi = 0; mi < 4; mi++)
#pragma unroll
        for (int ni = 0; ni < 2; ni++)
            wmma::store_matrix_sync(Cs + (wm * 64 + mi * 16) * 132 + wn * 32 + ni * 16,
                                    acc[mi][ni], 132, wmma::mem_row_major);
    __syncthreads();

    int col = tid & 127, rr = tid >> 7;
    if (OP & 8) {
        __nv_bfloat16* dst = (n0 < 512) ? (__nv_bfloat16*)Cv : (__nv_bfloat16*)C2v;
        int nloc = n0 & 511;
#pragma unroll 4
        for (int r = rr; r < 128; r += 2) {
            float v = Cs[r * 132 + col] + sbias[col];
            dst[(size_t)(m0 + r) * 512 + nloc + col] = f2b(gelu_f(v));
        }
    } else if (OP & 16) {
        const float* Rp = res + (size_t)m0 * N + n0 + col;
#pragma unroll 4
        for (int r = rr; r < 128; r += 2) {
            float v = Cs[r * 132 + col] + sbias[col] + Rp[(size_t)r * N];
            Cs[r * 132 + col] = v;
        }
        __syncthreads();
        int b = m0 >> 12, pix0 = m0 & 4095;
        float* outp = (float*)Cv + (size_t)b * Cq * Nq + pix0;
        int ch = tid >> 7;
        int m = tid & 127;
#pragma unroll 4
        for (int cc = 0; cc < 64; cc++) {
            int c = cc * 2 + ch;
            outp[(size_t)(n0 + c) * Nq + m] = Cs[m * 132 + c];
        }
    } else if (OP & 32) {
        __nv_bfloat16* dst = (__nv_bfloat16*)Cv;
#pragma unroll 4
        for (int r = rr; r < 128; r += 2)
            dst[(size_t)(m0 + r) * N + n0 + col] = f2b(Cs[r * 132 + col]);
    } else {
        float* Cp = (float*)Cv + (size_t)m0 * N + n0 + col;
        const float* Rp = res + (size_t)m0 * N + n0 + col;
#pragma unroll 4
        for (int r = rr; r < 128; r += 2) {
            float v = Cs[r * 132 + col];
            if (OP & 1) v += sbias[col];
            if (OP & 2) v = gelu_f(v);
            if (OP & 4) v += Rp[(size_t)r * N];
            Cp[(size_t)r * N] = v;
        }
    }
}

// ---------------- merged weight transposes ----------------
__global__ void k_wt_all(const float* __restrict__ qw, const float* __restrict__ pw,
                         const float* __restrict__ f1w, const float* __restrict__ f2w,
                         __nv_bfloat16* __restrict__ wtq, __nv_bfloat16* __restrict__ wtp,
                         __nv_bfloat16* __restrict__ wt1, __nv_bfloat16* __restrict__ wt2) {
    __shared__ float t[32][33];
    int bid = blockIdx.x;
    const float* w; __nv_bfloat16* wt; int K, N, bx, by;
    if (bid < 32)        { w = qw;  wt = wtq; K = 256; N = 128;  int l = bid;       bx = l & 3;  by = l >> 2; }
    else if (bid < 96)   { w = pw;  wt = wtp; K = 256; N = 256;  int l = bid - 32;  bx = l & 7;  by = l >> 3; }
    else if (bid < 352)  { w = f1w; wt = wt1; K = 256; N = 1024; int l = bid - 96;  bx = l & 31; by = l >> 5; }
    else                 { w = f2w; wt = wt2; K = 512; N = 256;  int l = bid - 352; bx = l & 7;  by = l >> 3; }
    int nb = bx * 32, kb = by * 32;
    int tx = threadIdx.x, ty = threadIdx.y;
#pragma unroll
    for (int j = 0; j < 4; j++)
        t[ty + j * 8][tx] = w[(size_t)(kb + ty + j * 8) * N + nb + tx];
    __syncthreads();
#pragma unroll
    for (int j = 0; j < 4; j++)
        wt[(size_t)(nb + ty + j * 8) * K + kb + tx] = f2b(t[tx][ty + j * 8]);
}

// ---------------- K1: coordinate pooled means ----------------
__global__ void k_mean(const float* __restrict__ x, float* __restrict__ mh, float* __restrict__ mw) {
    int bc = blockIdx.x;
    const float* p = x + (size_t)bc * 4096;
    int w = threadIdx.x;
    __shared__ float part[128];
    float colsum = 0.f;
    for (int r = 0; r < 64; r++) {
        float v = p[r * 64 + w];
        colsum += v;
        float s = v;
#pragma unroll
        for (int o = 16; o > 0; o >>= 1) s += __shfl_down_sync(0xffffffffu, s, o);
        if ((w & 31) == 0) part[(w >> 5) * 64 + r] = s;
    }
    __syncthreads();
    mh[(size_t)bc * 64 + w] = (part[w] + part[64 + w]) * (1.f / 64.f);
    mw[(size_t)bc * 64 + w] = colsum * (1.f / 64.f);
}

// ---------------- K2: dwconv1d(k=7) + GroupNorm(16) + ReLU ----------------
__global__ void k_sdagn(const float* __restrict__ mh, const float* __restrict__ mw,
                        const float* __restrict__ w7, const float* __restrict__ gnw,
                        const float* __restrict__ gnb, float* __restrict__ gh, float* __restrict__ gw_) {
    int grp = blockIdx.x, b = blockIdx.y;
    const float* mean = (blockIdx.z ? mw : mh) + (size_t)b * Cq * 64;
    float* out = (blockIdx.z ? gw_ : gh) + (size_t)b * Cq * 64;
    __shared__ float buf[1024];
    __shared__ float sh[64];
    int tid = threadIdx.x;
    float ls = 0.f, lq = 0.f;
#pragma unroll
    for (int j = 0; j < 4; j++) {
        int idx = tid + j * 256;
        int c = grp * 16 + (idx >> 6), l = idx & 63;
        const float* m = mean + c * 64;
        float acc = 0.f;
#pragma unroll
        for (int k = 0; k < 7; k++) {
            int ll = l + k - 3;
            if (ll >= 0 && ll < 64) acc += m[ll] * w7[c * 7 + k];
        }
        buf[idx] = acc; ls += acc; lq += acc * acc;
    }
    blockReduce2(ls, lq, sh);
    float mu = ls * (1.f / 1024.f);
    float rstd = rsqrtf(lq * (1.f / 1024.f) - mu * mu + 1e-5f);
#pragma unroll
    for (int j = 0; j < 4; j++) {
        int idx = tid + j * 256;
        int c = grp * 16 + (idx >> 6), l = idx & 63;
        float y = (buf[idx] - mu) * rstd * gnw[c] + gnb[c];
        out[(size_t)c * 64 + l] = fmaxf(y, 0.f);
    }
}

// ---------------- K3: modulate + to tokens + LN1 ----------------
__global__ void k_tokens(const float* __restrict__ x, const float* __restrict__ gh,
                         const float* __restrict__ gw_, const float* __restrict__ n1w,
                         const float* __restrict__ n1b, float* __restrict__ res,
                         __nv_bfloat16* __restrict__ ln) {
    int b = blockIdx.y;
    int n0 = blockIdx.x * 32;
    int h = n0 >> 6, w0 = n0 & 63;
    int nx = threadIdx.x, cy = threadIdx.y;
    __shared__ float tile[256][33];
    __shared__ float mu[32], rs[32];
    const float* ghb = gh + (size_t)b * Cq * 64;
    const float* gwb = gw_ + (size_t)b * Cq * 64;
    const float* xb = x + (size_t)b * Cq * Nq;
#pragma unroll 4
    for (int j = 0; j < 32; j++) {
        int c = cy * 32 + j;
        float v = xb[(size_t)c * Nq + h * 64 + w0 + nx] * ghb[c * 64 + h] * gwb[c * 64 + w0 + nx];
        tile[c][nx] = v;
    }
    __syncthreads();
    int tid = cy * 32 + nx, lane = tid & 31, warp = tid >> 5;
    for (int nn = warp; nn < 32; nn += 8) {
        float s = 0.f, q = 0.f;
        for (int c = lane; c < 256; c += 32) { float v = tile[c][nn]; s += v; q += v * v; }
#pragma unroll
        for (int o = 16; o > 0; o >>= 1) {
            s += __shfl_down_sync(0xffffffffu, s, o);
            q += __shfl_down_sync(0xffffffffu, q, o);
        }
        if (lane == 0) {
            float m = s * (1.f / 256.f);
            mu[nn] = m; rs[nn] = rsqrtf(q * (1.f / 256.f) - m * m + 1e-6f);
        }
    }
    __syncthreads();
    float* resp = res + ((size_t)b * Nq + n0) * Cq;
    __nv_bfloat16* lnp = ln + ((size_t)b * Nq + n0) * Cq;
    for (int idx = tid; idx < 32 * 256; idx += 256) {
        int nl = idx >> 8, c = idx & 255;
        float v = tile[c][nl];
        resp[(size_t)nl * 256 + c] = v;
        lnp[(size_t)nl * 256 + c] = f2b((v - mu[nl]) * rs[nl] * n1w[c] + n1b[c]);
    }
}

// ---------------- reduction path ----------------
__global__ void k_red1(const __nv_bfloat16* __restrict__ ln1, const float* __restrict__ rw,
                       const float* __restrict__ rb, float* __restrict__ r1) {
    int p = blockIdx.x, b = blockIdx.y, c = threadIdx.x;
    int i = p >> 4, j = p & 15;
    float acc = rb[c];
    const __nv_bfloat16* base = ln1 + (size_t)b * Nq * Cq + c;
#pragma unroll
    for (int a = 0; a < 4; a++)
#pragma unroll
        for (int d = 0; d < 4; d++) {
            int n = (4 * i + a) * 64 + 4 * j + d;
            acc += __bfloat162float(base[(size_t)n * 256]) * rw[c * 16 + a * 4 + d];
        }
    r1[((size_t)b * 256 + p) * 256 + c] = acc;
}

__global__ void k_red2(const float* __restrict__ r1, const float* __restrict__ rw,
                       const float* __restrict__ rb, float* __restrict__ r2) {
    int p2 = blockIdx.x, b = blockIdx.y, c = threadIdx.x;
    int i2 = p2 >> 2, j2 = p2 & 3;
    float acc = rb[c];
#pragma unroll
    for (int a = 0; a < 4; a++)
#pragma unroll
        for (int d = 0; d < 4; d++) {
            int p = (4 * i2 + a) * 16 + (4 * j2 + d);
            acc += r1[((size_t)b * 256 + p) * 256 + c] * rw[c * 16 + a * 4 + d];
        }
    r2[((size_t)b * 16 + p2) * 256 + c] = acc;
}

__global__ void k_dw3(const float* __restrict__ r2, const float* __restrict__ dww,
                      const float* __restrict__ dwb, float* __restrict__ dd) {
    int p = blockIdx.x, b = blockIdx.y, c = threadIdx.x;
    int i = p >> 2, j = p & 3;
    float acc = dwb[c];
#pragma unroll
    for (int a = 0; a < 3; a++) {
        int ii = i + a - 1;
        if (ii < 0 || ii >= 4) continue;
#pragma unroll
        for (int d = 0; d < 3; d++) {
            int jj = j + d - 1;
            if (jj < 0 || jj >= 4) continue;
            acc += r2[((size_t)b * 16 + ii * 4 + jj) * 256 + c] * dww[c * 9 + a * 3 + d];
        }
    }
    dd[((size_t)b * 16 + p) * 256 + c] = acc;
}

// fused na (1x1 256->128 + LN128 + gelu, kept in smem) + k/v projections
__global__ void k_nakv(const float* __restrict__ dd, const float* __restrict__ cw,
                       const float* __restrict__ cb, const float* __restrict__ naw,
                       const float* __restrict__ nab, const float* __restrict__ kw,
                       const float* __restrict__ vw, float* __restrict__ kk,
                       float* __restrict__ vt) {
    int p = blockIdx.x, b = blockIdx.y, t = threadIdx.x;
    __shared__ float ds[256];
    __shared__ float xs[128];
    __shared__ float sh[64];
    const float* dp = dd + ((size_t)b * 16 + p) * 256;
    ds[t] = dp[t];
    __syncthreads();
    float e = 0.f, s = 0.f, q = 0.f;
    if (t < 128) {
        e = cb[t];
        for (int c = 0; c < 256; c++) e += ds[c] * cw[t * 256 + c];
        s = e; q = e * e;
    }
    blockReduce2(s, q, sh);
    float mu = s * (1.f / 128.f);
    float rstd = rsqrtf(q * (1.f / 128.f) - mu * mu + 1e-5f);
    if (t < 128) xs[t] = gelu_f((e - mu) * rstd * naw[t] + nab[t]);
    __syncthreads();
    if (t < 128) {
        float a = 0.f;
        for (int c = 0; c < 128; c++) a += xs[c] * kw[c * 128 + t];
        kk[((size_t)b * 16 + p) * 128 + t] = a;
    }
    float a2 = 0.f;
    for (int c = 0; c < 128; c++) a2 += xs[c] * vw[c * 256 + t];
    vt[((size_t)b * 16 + p) * 256 + t] = a2;
}

__global__ void k_cpe(const float* __restrict__ vt, const float* __restrict__ cw,
                      const float* __restrict__ cb, float* __restrict__ v2) {
    int p = blockIdx.x, b = blockIdx.y, ch = threadIdx.x;
    int i = p >> 2, j = p & 3;
    float acc = cb[ch];
#pragma unroll
    for (int a = 0; a < 3; a++) {
        int ii = i + a - 1;
        if (ii < 0 || ii >= 4) continue;
#pragma unroll
        for (int d = 0; d < 3; d++) {
            int jj = j + d - 1;
            if (jj < 0 || jj >= 4) continue;
            acc += vt[((size_t)b * 16 + ii * 4 + jj) * 256 + ch] * cw[ch * 9 + a * 3 + d];
        }
    }
    v2[((size_t)b * 16 + p) * 256 + ch] = vt[((size_t)b * 16 + p) * 256 + ch] + acc;
}

// ---------------- fused attention (vectorized IO) ----------------
__global__ void k_attn(const __nv_bfloat16* __restrict__ q, const float* __restrict__ kk,
                       const float* __restrict__ v2, __nv_bfloat16* __restrict__ ao) {
    __shared__ __align__(16) float ks[8 * 260];
    __shared__ __align__(16) float vs[8 * 516];
    int b = blockIdx.y;
    int tid = threadIdx.x;
    const float4* kk4 = (const float4*)(kk + (size_t)b * 2048);
    for (int f = tid; f < 512; f += 256) {
        float4 v = kk4[f];
        int head = f >> 6, rem = f & 63, m = rem >> 2, ig = (rem & 3) * 4;
        *(float4*)&ks[head * 260 + m * 16 + ig] = v;
    }
    const float4* v24 = (const float4*)(v2 + (size_t)b * 4096);
    for (int f = tid; f < 1024; f += 256) {
        float4 v = v24[f];
        int head = f >> 7, rem = f & 127, m = rem >> 3, dg = (rem & 7) * 4;
        *(float4*)&vs[head * 516 + m * 32 + dg] = v;
    }
    __syncthreads();
    int nl = tid >> 3, head = tid & 7;
    int n = blockIdx.x * 32 + nl;
    const __nv_bfloat16* qp = q + ((size_t)b * Nq + n) * 128 + head * 16;
    uint4 q0 = ((const uint4*)qp)[0], q1 = ((const uint4*)qp)[1];
    float qr[16];
    {
        const unsigned* qa = (const unsigned*)&q0;
#pragma unroll
        for (int i = 0; i < 4; i++) {
            __nv_bfloat162 h = *(const __nv_bfloat162*)&qa[i];
            qr[i * 2] = __bfloat162float(h.x); qr[i * 2 + 1] = __bfloat162float(h.y);
        }
        const unsigned* qb2 = (const unsigned*)&q1;
#pragma unroll
        for (int i = 0; i < 4; i++) {
            __nv_bfloat162 h = *(const __nv_bfloat162*)&qb2[i];
            qr[8 + i * 2] = __bfloat162float(h.x); qr[8 + i * 2 + 1] = __bfloat162float(h.y);
        }
    }
    const float* kh = ks + head * 260;
    float s[16];
    float mx = -1e30f;
#pragma unroll
    for (int m = 0; m < 16; m++) {
        float a = 0.f;
#pragma unroll
        for (int i = 0; i < 16; i++) a += qr[i] * kh[m * 16 + i];
        a *= 0.25f;
        s[m] = a;
        mx = fmaxf(mx, a);
    }
    float sum = 0.f;
#pragma unroll
    for (int m = 0; m < 16; m++) { s[m] = __expf(s[m] - mx); sum += s[m]; }
    float inv = 1.f / sum;
    float o[32];
#pragma unroll
    for (int d = 0; d < 32; d++) o[d] = 0.f;
    const float* vh = vs + head * 516;
#pragma unroll
    for (int m = 0; m < 16; m++) {
        float pm = s[m] * inv;
#pragma unroll
        for (int d = 0; d < 32; d++) o[d] += pm * vh[m * 32 + d];
    }
    uint4* op4 = (uint4*)(ao + ((size_t)b * Nq + n) * 256 + head * 32);
#pragma unroll
    for (int g = 0; g < 4; g++) {
        uint4 u;
        u.x = pk2(o[g * 8 + 0], o[g * 8 + 1]);
        u.y = pk2(o[g * 8 + 2], o[g * 8 + 3]);
        u.z = pk2(o[g * 8 + 4], o[g * 8 + 5]);
        u.w = pk2(o[g * 8 + 6], o[g * 8 + 7]);
        op4[g] = u;
    }
}

// ---------------- warp-per-row LayerNorm f32 -> bf16, D=256 ----------------
// grid Mrows/8, block 256 (8 warps, one row each)
__global__ void k_ln(const float* __restrict__ in, const float* __restrict__ w,
                     const float* __restrict__ b, __nv_bfloat16* __restrict__ out, float eps) {
    int warp = threadIdx.x >> 5, lane = threadIdx.x & 31;
    size_t row = (size_t)blockIdx.x * 8 + warp;
    const float4* ip = (const float4*)(in + row * 256);
    float4 va = ip[lane], vb = ip[lane + 32];
    float s = va.x + va.y + va.z + va.w + vb.x + vb.y + vb.z + vb.w;
    float q = va.x * va.x + va.y * va.y + va.z * va.z + va.w * va.w
            + vb.x * vb.x + vb.y * vb.y + vb.z * vb.z + vb.w * vb.w;
#pragma unroll
    for (int o = 16; o > 0; o >>= 1) {
        s += __shfl_xor_sync(0xffffffffu, s, o);
        q += __shfl_xor_sync(0xffffffffu, q, o);
    }
    float mu = s * (1.f / 256.f);
    float rstd = rsqrtf(q * (1.f / 256.f) - mu * mu + eps);
    const float4* wp = (const float4*)w;
    const float4* bp = (const float4*)b;
    float4 w0 = wp[lane], w1 = wp[lane + 32];
    float4 b0 = bp[lane], b1 = bp[lane + 32];
    uint2* op = (uint2*)(out + row * 256);
    uint2 u;
    u.x = pk2((va.x - mu) * rstd * w0.x + b0.x, (va.y - mu) * rstd * w0.y + b0.y);
    u.y = pk2((va.z - mu) * rstd * w0.z + b0.z, (va.w - mu) * rstd * w0.w + b0.w);
    op[lane] = u;
    u.x = pk2((vb.x - mu) * rstd * w1.x + b1.x, (vb.y - mu) * rstd * w1.y + b1.y);
    u.y = pk2((vb.z - mu) * rstd * w1.z + b1.z, (vb.w - mu) * rstd * w1.w + b1.w);
    op[lane + 32] = u;
}

// ---------------- warp-per-row LayerNorm bf16 -> bf16, D=512 ----------------
// grid Mrows/8, block 256
__global__ void k_lnb(const __nv_bfloat16* __restrict__ in, const float* __restrict__ w,
                      const float* __restrict__ b, __nv_bfloat16* __restrict__ out, float eps) {
    int warp = threadIdx.x >> 5, lane = threadIdx.x & 31;
    size_t row = (size_t)blockIdx.x * 8 + warp;
    const uint4* ip = (const uint4*)(in + row * 512);
    uint4 u0 = ip[lane], u1 = ip[lane + 32];
    float v[16];
    {
        const unsigned* ua = (const unsigned*)&u0;
#pragma unroll
        for (int i = 0; i < 4; i++) {
            __nv_bfloat162 h = *(const __nv_bfloat162*)&ua[i];
            v[i * 2] = __bfloat162float(h.x); v[i * 2 + 1] = __bfloat162float(h.y);
        }
        const unsigned* ub = (const unsigned*)&u1;
#pragma unroll
        for (int i = 0; i < 4; i++) {
            __nv_bfloat162 h = *(const __nv_bfloat162*)&ub[i];
            v[8 + i * 2] = __bfloat162float(h.x); v[8 + i * 2 + 1] = __bfloat162float(h.y);
        }
    }
    float s = 0.f, q = 0.f;
#pragma unroll
    for (int i = 0; i < 16; i++) { s += v[i]; q += v[i] * v[i]; }
#pragma unroll
    for (int o = 16; o > 0; o >>= 1) {
        s += __shfl_xor_sync(0xffffffffu, s, o);
        q += __shfl_xor_sync(0xffffffffu, q, o);
    }
    float mu = s * (1.f / 512.f);
    float rstd = rsqrtf(q * (1.f / 512.f) - mu * mu + eps);
    int c0 = lane * 8, c1 = (lane + 32) * 8;
    uint4* op = (uint4*)(out + row * 512);
    uint4 ou;
    ou.x = pk2((v[0] - mu) * rstd * w[c0 + 0] + b[c0 + 0], (v[1] - mu) * rstd * w[c0 + 1] + b[c0 + 1]);
    ou.y = pk2((v[2] - mu) * rstd * w[c0 + 2] + b[c0 + 2], (v[3] - mu) * rstd * w[c0 + 3] + b[c0 + 3]);
    ou.z = pk2((v[4] - mu) * rstd * w[c0 + 4] + b[c0 + 4], (v[5] - mu) * rstd * w[c0 + 5] + b[c0 + 5]);
    ou.w = pk2((v[6] - mu) * rstd * w[c0 + 6] + b[c0 + 6], (v[7] - mu) * rstd * w[c0 + 7] + b[c0 + 7]);
    op[lane] = ou;
    ou.x = pk2((v[8] - mu) * rstd * w[c1 + 0] + b[c1 + 0], (v[9] - mu) * rstd * w[c1 + 1] + b[c1 + 1]);
    ou.y = pk2((v[10] - mu) * rstd * w[c1 + 2] + b[c1 + 2], (v[11] - mu) * rstd * w[c1 + 3] + b[c1 + 3]);
    ou.z = pk2((v[12] - mu) * rstd * w[c1 + 4] + b[c1 + 4], (v[13] - mu) * rstd * w[c1 + 5] + b[c1 + 5]);
    ou.w = pk2((v[14] - mu) * rstd * w[c1 + 6] + b[c1 + 6], (v[15] - mu) * rstd * w[c1 + 7] + b[c1 + 7]);
    op[lane + 32] = ou;
}

// ---------------- depthwise 3x3 gate conv + multiply (bf162-vectorized) ----------------
__global__ void k_gconv(const __nv_bfloat16* __restrict__ x2, const __nv_bfloat16* __restrict__ x1,
                        const float* __restrict__ gcw, const float* __restrict__ gcb,
                        __nv_bfloat16* __restrict__ gated) {
    int n = blockIdx.x, b = blockIdx.y;
    int hh = n >> 6, ww = n & 63;
    int ch = threadIdx.x * 2;
    const __nv_bfloat16* xb = x2 + (size_t)b * Nq * 512 + ch;
    float a0 = gcb[ch], a1 = gcb[ch + 1];
#pragma unroll
    for (int a = 0; a < 3; a++) {
        int hi = hh + a - 1;
        if (hi < 0 || hi >= 64) continue;
#pragma unroll
        for (int d = 0; d < 3; d++) {
            int wi = ww + d - 1;
            if (wi < 0 || wi >= 64) continue;
            __nv_bfloat162 v = *(const __nv_bfloat162*)(xb + (size_t)(hi * 64 + wi) * 512);
            a0 += __bfloat162float(v.x) * gcw[ch * 9 + a * 3 + d];
            a1 += __bfloat162float(v.y) * gcw[(ch + 1) * 9 + a * 3 + d];
        }
    }
    __nv_bfloat162 g1 = *(const __nv_bfloat162*)(x1 + ((size_t)b * Nq + n) * 512 + ch);
    __nv_bfloat162 o;
    o.x = f2b(__bfloat162float(g1.x) * a0);
    o.y = f2b(__bfloat162float(g1.y) * a1);
    *(__nv_bfloat162*)(gated + ((size_t)b * Nq + n) * 512 + ch) = o;
}

// ---------------- host launch ----------------
extern "C" void kernel_launch(void* const* d_in, const int* in_sizes, int n_in,
                              void* d_out, int out_size) {
    const float* x          = (const float*)d_in[0];
    const float* sda_conv_w = (const float*)d_in[1];
    const float* sda_gn_w   = (const float*)d_in[2];
    const float* sda_gn_b   = (const float*)d_in[3];
    const float* norm1_w    = (const float*)d_in[4];
    const float* norm1_b    = (const float*)d_in[5];
    const float* red_w      = (const float*)d_in[6];
    const float* red_b      = (const float*)d_in[7];
    const float* dw_w       = (const float*)d_in[8];
    const float* dw_b       = (const float*)d_in[9];
    const float* conv_w     = (const float*)d_in[10];
    const float* conv_b     = (const float*)d_in[11];
    const float* na_w       = (const float*)d_in[12];
    const float* na_b       = (const float*)d_in[13];
    const float* q_w        = (const float*)d_in[14];
    const float* k_w        = (const float*)d_in[15];
    const float* v_w        = (const float*)d_in[16];
    const float* cpe_w      = (const float*)d_in[17];
    const float* cpe_b      = (const float*)d_in[18];
    const float* proj_w     = (const float*)d_in[19];
    const float* proj_b     = (const float*)d_in[20];
    const float* norm2_w    = (const float*)d_in[21];
    const float* norm2_b    = (const float*)d_in[22];
    const float* fc1_w      = (const float*)d_in[23];
    const float* fc1_b      = (const float*)d_in[24];
    const float* gnorm_w    = (const float*)d_in[25];
    const float* gnorm_b    = (const float*)d_in[26];
    const float* gconv_w    = (const float*)d_in[27];
    const float* gconv_b    = (const float*)d_in[28];
    const float* fc2_w      = (const float*)d_in[29];
    const float* fc2_b      = (const float*)d_in[30];

    float* S;
    cudaGetSymbolAddress((void**)&S, g_s);
    float* mh   = S + OFF_MH;
    float* mw   = S + OFF_MW;
    float* gh   = S + OFF_GH;
    float* gw   = S + OFF_GW;
    float* res1 = S + OFF_RES1;
    __nv_bfloat16* lnb  = (__nv_bfloat16*)(S + OFF_LNB);
    __nv_bfloat16* qb   = (__nv_bfloat16*)(S + OFF_QB);
    float* r1   = S + OFF_R1;
    float* r2   = S + OFF_R2;
    float* dd   = S + OFF_D;
    float* kk   = S + OFF_K;
    float* vt   = S + OFF_VT;
    float* v2   = S + OFF_V2;
    __nv_bfloat16* aob  = (__nv_bfloat16*)(S + OFF_AOB);
    float* t2   = S + OFF_T2;
    __nv_bfloat16* ln2b = (__nv_bfloat16*)(S + OFF_LN2B);
    __nv_bfloat16* x1b  = (__nv_bfloat16*)(S + OFF_X1B);
    __nv_bfloat16* x2b  = (__nv_bfloat16*)(S + OFF_X2B);
    __nv_bfloat16* x2ln = (__nv_bfloat16*)(S + OFF_X2LN);
    __nv_bfloat16* gtb  = (__nv_bfloat16*)(S + OFF_GTB);
    __nv_bfloat16* wtq  = (__nv_bfloat16*)(S + OFF_WTQ);
    __nv_bfloat16* wtp  = (__nv_bfloat16*)(S + OFF_WTP);
    __nv_bfloat16* wt1  = (__nv_bfloat16*)(S + OFF_WT1);
    __nv_bfloat16* wt2  = (__nv_bfloat16*)(S + OFF_WT2);

    cudaFuncSetAttribute(k_bf_gemm<32>, cudaFuncAttributeMaxDynamicSharedMemorySize, DSMB);
    cudaFuncSetAttribute(k_bf_gemm<5>,  cudaFuncAttributeMaxDynamicSharedMemorySize, DSMB);
    cudaFuncSetAttribute(k_bf_gemm<11>, cudaFuncAttributeMaxDynamicSharedMemorySize, DSMB);
    cudaFuncSetAttribute(k_bf_gemm<21>, cudaFuncAttributeMaxDynamicSharedMemorySize, DSMB);

    // weight transposes -> bf16 K-major (single merged launch)
    k_wt_all<<<480, dim3(32, 8)>>>(q_w, proj_w, fc1_w, fc2_w, wtq, wtp, wt1, wt2);

    // SDAM
    k_mean<<<Bq * Cq, 64>>>(x, mh, mw);
    k_sdagn<<<dim3(16, Bq, 2), 256>>>(mh, mw, sda_conv_w, sda_gn_w, sda_gn_b, gh, gw);
    k_tokens<<<dim3(128, Bq), dim3(32, 8)>>>(x, gh, gw, norm1_w, norm1_b, res1, lnb);

    // reduced path
    k_red1<<<dim3(256, Bq), 256>>>(lnb, red_w, red_b, r1);
    k_red2<<<dim3(16, Bq), 256>>>(r1, red_w, red_b, r2);
    k_dw3<<<dim3(16, Bq), 256>>>(r2, dw_w, dw_b, dd);
    k_nakv<<<dim3(16, Bq), 256>>>(dd, conv_w, conv_b, na_w, na_b, k_w, v_w, kk, vt);
    k_cpe<<<dim3(16, Bq), 256>>>(vt, cpe_w, cpe_b, v2);

    // q projection -> bf16 (M, 128, K=256)
    k_bf_gemm<32><<<dim3(1, Mrows / 128), 256, DSMB>>>(lnb, wtq, nullptr, nullptr, qb, nullptr, Mrows, 128, 256);

    // attention
    k_attn<<<dim3(128, Bq), 256>>>(qb, kk, v2, aob);

    // proj + bias + residual -> f32 t2
    k_bf_gemm<5><<<dim3(2, Mrows / 128), 256, DSMB>>>(aob, wtp, proj_b, res1, t2, nullptr, Mrows, 256, 256);

    // MLP
    k_ln<<<Mrows / 8, 256>>>(t2, norm2_w, norm2_b, ln2b, 1e-6f);
    k_bf_gemm<11><<<dim3(8, Mrows / 128), 256, DSMB>>>(ln2b, wt1, fc1_b, nullptr, x1b, x2b, Mrows, 1024, 256);
    k_lnb<<<Mrows / 8, 256>>>(x2b, gnorm_w, gnorm_b, x2ln, 1e-5f);
    k_gconv<<<dim3(4096, Bq), 256>>>(x2ln, x1b, gconv_w, gconv_b, gtb);
    // fc2 + bias + residual, fused transpose -> d_out [B,C,H,W]
    k_bf_gemm<21><<<dim3(2, Mrows / 128), 256, DSMB>>>(gtb, wt2, fc2_b, t2, d_out, nullptr, Mrows, 256, 512);
}